// round 8
// baseline (speedup 1.0000x reference)
#include <cuda_runtime.h>
#include <cstdint>
#include <math.h>

#define D_DIM 2048
#define B_TOK 4096

// ---------------- scratch (device globals; no allocation allowed) ----------
__device__ float g_srcR[(size_t)B_TOK * D_DIM];
__device__ float g_srcT[(size_t)B_TOK * D_DIM];
__device__ float g_thkR[(size_t)D_DIM * D_DIM];
__device__ float g_thqR[(size_t)D_DIM * D_DIM];
__device__ float g_WR  [(size_t)D_DIM * D_DIM];
__device__ float g_thkT[(size_t)D_DIM * D_DIM];
__device__ float g_S   [(size_t)D_DIM * D_DIM];
__device__ float g_M   [(size_t)D_DIM * D_DIM];
__device__ float g_T1  [(size_t)D_DIM * D_DIM];
__device__ float g_MT  [(size_t)D_DIM * D_DIM];
__device__ float g_T1T [(size_t)D_DIM * D_DIM];
__device__ float g_Wn  [(size_t)D_DIM * D_DIM];
__device__ float g_P   [(size_t)D_DIM * D_DIM];
__device__ float g_PT  [(size_t)D_DIM * D_DIM];
__device__ float g_part[32 * D_DIM];
__device__ float g_c   [D_DIM];
__device__ float g_v   [D_DIM];
__device__ float g_bn  [D_DIM];

// ---------------- PTX helpers ----------------------------------------------
__device__ __forceinline__ float rnd_tf32(float x) {
    uint32_t r;
    asm("cvt.rna.tf32.f32 %0, %1;" : "=r"(r) : "f"(x));
    return __uint_as_float(r);
}

__device__ __forceinline__ void cp16(uint32_t dst, const float* src) {
    asm volatile("cp.async.cg.shared.global [%0], [%1], 16;" :: "r"(dst), "l"(src));
}

__device__ __forceinline__ void ldsm4(uint32_t& r0, uint32_t& r1, uint32_t& r2, uint32_t& r3,
                                      uint32_t addr) {
    asm volatile("ldmatrix.sync.aligned.m8n8.x4.shared.b16 {%0,%1,%2,%3}, [%4];"
                 : "=r"(r0), "=r"(r1), "=r"(r2), "=r"(r3) : "r"(addr));
}

__device__ __forceinline__ void mma_tf32(float c[4], const uint32_t a[4],
                                         uint32_t b0, uint32_t b1) {
    asm volatile(
        "mma.sync.aligned.m16n8k8.row.col.f32.tf32.tf32.f32 "
        "{%0,%1,%2,%3}, {%4,%5,%6,%7}, {%8,%9}, {%0,%1,%2,%3};"
        : "+f"(c[0]), "+f"(c[1]), "+f"(c[2]), "+f"(c[3])
        : "r"(a[0]), "r"(a[1]), "r"(a[2]), "r"(a[3]), "r"(b0), "r"(b1));
}

// ---------------------------------------------------------------------------
// Wide NT tf32 GEMM: C[M,N] = A[M,K]*B[N,K]^T. CTA 128x256, 8 warps of 64x64,
// BK=32, 4-stage cp.async (192KB smem, occ 1). Inputs pre-rounded to tf32.
// Pipeline order per k-tile: wait_group -> syncthreads -> loadTile(t+3)
// (load AFTER the barrier: stage (t+3)&3 == (t-1)&3 must be fully read first).
// EPI 0: C = acc
// EPI 1: C = acc + e1[idx] - e2[idx]
// EPI 2: C = e1[idx] - e2[idx] * coef * (acc + ev0[row]*ev1[col])
// EPI 3: C = acc + e1[idx]
// EPI 4: C = acc + e0[col]
// ---------------------------------------------------------------------------
template <int EPI, bool RND>
__global__ void __launch_bounds__(256, 1)
ntgemm2(const float* __restrict__ A, const float* __restrict__ B,
        float* __restrict__ C, int M, int N, int K,
        const float* __restrict__ e0, const float* __restrict__ e1,
        const float* __restrict__ e2, const float* __restrict__ ev0,
        const float* __restrict__ ev1, float coef)
{
    constexpr int BK    = 32;
    constexpr int ATILE = 128 * BK * 4;    // 16 KB
    constexpr int BTILE = 256 * BK * 4;    // 32 KB
    constexpr int SS    = ATILE + BTILE;   // 48 KB per stage

    extern __shared__ __align__(128) char smraw[];
    const uint32_t sb = (uint32_t)__cvta_generic_to_shared(smraw);

    const int tid  = threadIdx.x;
    const int lane = tid & 31;
    const int wid  = tid >> 5;
    const int wm   = (wid & 1) * 64;
    const int wn   = (wid >> 1) * 64;
    const int m0   = blockIdx.y * 128;
    const int n0   = blockIdx.x * 256;

    const int lr = tid >> 3;
    const int lc = tid & 7;
    const uint32_t lOff = (uint32_t)(lr * 128 + ((lc ^ (lr & 7)) << 4));
    const float* aG = A + (size_t)(m0 + lr) * K + lc * 4;
    const float* bG = B + (size_t)(n0 + lr) * K + lc * 4;

    auto loadTile = [&](int t) {
        const uint32_t base = sb + (uint32_t)((t & 3) * SS);
        const float* a = aG + (size_t)t * BK;
        const float* b = bG + (size_t)t * BK;
#pragma unroll
        for (int i = 0; i < 4; ++i)
            cp16(base + lOff + 4096u * i, a + (size_t)(32 * i) * K);
#pragma unroll
        for (int i = 0; i < 8; ++i)
            cp16(base + ATILE + lOff + 4096u * i, b + (size_t)(32 * i) * K);
        asm volatile("cp.async.commit_group;" ::: "memory");
    };

    const int rr  = lane & 7;
    const int loA = (lane >> 3) & 1;
    const int hiA = (lane >> 4) & 1;
    const int loB = (lane >> 4) & 1;
    const int hiB = (lane >> 3) & 1;
    const uint32_t swz = (uint32_t)rr << 4;

    uint32_t aRow[4], bRow[4];
#pragma unroll
    for (int mf = 0; mf < 4; ++mf)
        aRow[mf] = (uint32_t)((wm + mf * 16 + loA * 8 + rr) * 128);
#pragma unroll
    for (int nfp = 0; nfp < 4; ++nfp)
        bRow[nfp] = (uint32_t)((wn + nfp * 16 + loB * 8 + rr) * 128);

    float acc[4][8][4];
#pragma unroll
    for (int i = 0; i < 4; ++i)
#pragma unroll
        for (int j = 0; j < 8; ++j)
#pragma unroll
            for (int k = 0; k < 4; ++k) acc[i][j][k] = 0.0f;

    const int nt = K / BK;
    loadTile(0);
    loadTile(1);
    loadTile(2);

    for (int t = 0; t < nt; ++t) {
        if (t + 2 < nt)      asm volatile("cp.async.wait_group 2;" ::: "memory");
        else if (t + 1 < nt) asm volatile("cp.async.wait_group 1;" ::: "memory");
        else                 asm volatile("cp.async.wait_group 0;" ::: "memory");
        __syncthreads();
        if (t + 3 < nt) loadTile(t + 3);   // safe: stage (t-1)&3 fully consumed

        const uint32_t stA = sb + (uint32_t)((t & 3) * SS);
        const uint32_t stB = stA + ATILE;

#pragma unroll
        for (int kk = 0; kk < 4; ++kk) {
            const uint32_t ak = (((uint32_t)(2 * kk + hiA)) << 4) ^ swz;
            const uint32_t bk = (((uint32_t)(2 * kk + hiB)) << 4) ^ swz;
            uint32_t af[4][4];
#pragma unroll
            for (int mf = 0; mf < 4; ++mf)
                ldsm4(af[mf][0], af[mf][1], af[mf][2], af[mf][3], stA + aRow[mf] + ak);
            uint32_t bf[4][4];
#pragma unroll
            for (int nfp = 0; nfp < 4; ++nfp)
                ldsm4(bf[nfp][0], bf[nfp][1], bf[nfp][2], bf[nfp][3], stB + bRow[nfp] + bk);
#pragma unroll
            for (int mf = 0; mf < 4; ++mf)
#pragma unroll
                for (int nf = 0; nf < 8; ++nf)
                    mma_tf32(acc[mf][nf], af[mf],
                             bf[nf >> 1][(nf & 1) * 2], bf[nf >> 1][(nf & 1) * 2 + 1]);
        }
    }

    // ---- epilogue ----
    const int g   = lane >> 2;
    const int tig = lane & 3;
#pragma unroll
    for (int mf = 0; mf < 4; ++mf) {
#pragma unroll
        for (int nf = 0; nf < 8; ++nf) {
#pragma unroll
            for (int h = 0; h < 2; ++h) {
                const int r = m0 + wm + mf * 16 + g + h * 8;
                const int c = n0 + wn + nf * 8 + 2 * tig;
                const size_t idx = (size_t)r * N + c;
                float v0 = acc[mf][nf][h * 2 + 0];
                float v1 = acc[mf][nf][h * 2 + 1];
                if (EPI == 1) {
                    const float2 a1 = *reinterpret_cast<const float2*>(e1 + idx);
                    const float2 a2 = *reinterpret_cast<const float2*>(e2 + idx);
                    v0 += a1.x - a2.x;
                    v1 += a1.y - a2.y;
                } else if (EPI == 2) {
                    const float2 w  = *reinterpret_cast<const float2*>(e1 + idx);
                    const float2 lr = *reinterpret_cast<const float2*>(e2 + idx);
                    const float bi  = ev0[r];
                    const float g0  = coef * (v0 + bi * ev1[c]);
                    const float g1  = coef * (v1 + bi * ev1[c + 1]);
                    v0 = w.x - lr.x * g0;
                    v1 = w.y - lr.y * g1;
                } else if (EPI == 3) {
                    const float2 a1 = *reinterpret_cast<const float2*>(e1 + idx);
                    v0 += a1.x;
                    v1 += a1.y;
                } else if (EPI == 4) {
                    v0 += e0[c];
                    v1 += e0[c + 1];
                }
                if (RND) { v0 = rnd_tf32(v0); v1 = rnd_tf32(v1); }
                float2 out; out.x = v0; out.y = v1;
                *reinterpret_cast<float2*>(C + idx) = out;
            }
        }
    }
}

// ---------------------------------------------------------------------------
// Symmetric Gram GEMM: CTA 128x128, 4-stage (race-fixed ordering).
// Computes lower-triangle tiles of C = A*A^T and mirrors off-diagonal blocks.
// ---------------------------------------------------------------------------
__global__ void __launch_bounds__(256, 1)
symgemm(const float* __restrict__ A, float* __restrict__ C, int N, int K)
{
    constexpr int BK   = 32;
    constexpr int TILE = 128 * BK * 4;
    constexpr int SS   = 2 * TILE;

    extern __shared__ __align__(128) char smraw[];
    const uint32_t sb = (uint32_t)__cvta_generic_to_shared(smraw);

    const int tid  = threadIdx.x;
    const int lane = tid & 31;
    const int wid  = tid >> 5;
    const int wm   = (wid & 1) * 64;
    const int wn   = (wid >> 1) * 32;

    const int i = blockIdx.x;
    int e = (int)((sqrtf(8.0f * (float)i + 1.0f) - 1.0f) * 0.5f);
    while ((e + 1) * (e + 2) / 2 <= i) ++e;
    while (e * (e + 1) / 2 > i) --e;
    const int by = e;
    const int bx = i - e * (e + 1) / 2;
    const int m0 = by * 128;
    const int n0 = bx * 128;

    const int lr = tid >> 3;
    const int lc = tid & 7;
    const uint32_t lOff = (uint32_t)(lr * 128 + ((lc ^ (lr & 7)) << 4));
    const float* aG = A + (size_t)(m0 + lr) * K + lc * 4;
    const float* bG = A + (size_t)(n0 + lr) * K + lc * 4;

    auto loadTile = [&](int t) {
        const uint32_t base = sb + (uint32_t)((t & 3) * SS);
        const float* a = aG + (size_t)t * BK;
        const float* b = bG + (size_t)t * BK;
#pragma unroll
        for (int ii = 0; ii < 4; ++ii)
            cp16(base + lOff + 4096u * ii, a + (size_t)(32 * ii) * K);
#pragma unroll
        for (int ii = 0; ii < 4; ++ii)
            cp16(base + TILE + lOff + 4096u * ii, b + (size_t)(32 * ii) * K);
        asm volatile("cp.async.commit_group;" ::: "memory");
    };

    const int rr  = lane & 7;
    const int loA = (lane >> 3) & 1;
    const int hiA = (lane >> 4) & 1;
    const int loB = (lane >> 4) & 1;
    const int hiB = (lane >> 3) & 1;
    const uint32_t swz = (uint32_t)rr << 4;

    uint32_t aRow[4], bRow[2];
#pragma unroll
    for (int mf = 0; mf < 4; ++mf)
        aRow[mf] = (uint32_t)((wm + mf * 16 + loA * 8 + rr) * 128);
#pragma unroll
    for (int nfp = 0; nfp < 2; ++nfp)
        bRow[nfp] = (uint32_t)((wn + nfp * 16 + loB * 8 + rr) * 128);

    float acc[4][4][4];
#pragma unroll
    for (int a = 0; a < 4; ++a)
#pragma unroll
        for (int b = 0; b < 4; ++b)
#pragma unroll
            for (int k = 0; k < 4; ++k) acc[a][b][k] = 0.0f;

    const int nt = K / BK;
    loadTile(0); loadTile(1); loadTile(2);

    for (int t = 0; t < nt; ++t) {
        if (t + 2 < nt)      asm volatile("cp.async.wait_group 2;" ::: "memory");
        else if (t + 1 < nt) asm volatile("cp.async.wait_group 1;" ::: "memory");
        else                 asm volatile("cp.async.wait_group 0;" ::: "memory");
        __syncthreads();
        if (t + 3 < nt) loadTile(t + 3);   // safe: stage fully consumed

        const uint32_t stA = sb + (uint32_t)((t & 3) * SS);
        const uint32_t stB = stA + TILE;

#pragma unroll
        for (int kk = 0; kk < 4; ++kk) {
            const uint32_t ak = (((uint32_t)(2 * kk + hiA)) << 4) ^ swz;
            const uint32_t bk = (((uint32_t)(2 * kk + hiB)) << 4) ^ swz;
            uint32_t af[4][4];
#pragma unroll
            for (int mf = 0; mf < 4; ++mf)
                ldsm4(af[mf][0], af[mf][1], af[mf][2], af[mf][3], stA + aRow[mf] + ak);
            uint32_t bf[2][4];
#pragma unroll
            for (int nfp = 0; nfp < 2; ++nfp)
                ldsm4(bf[nfp][0], bf[nfp][1], bf[nfp][2], bf[nfp][3], stB + bRow[nfp] + bk);
#pragma unroll
            for (int mf = 0; mf < 4; ++mf)
#pragma unroll
                for (int nf = 0; nf < 4; ++nf)
                    mma_tf32(acc[mf][nf], af[mf],
                             bf[nf >> 1][(nf & 1) * 2], bf[nf >> 1][(nf & 1) * 2 + 1]);
        }
    }

    const int g   = lane >> 2;
    const int tig = lane & 3;
#pragma unroll
    for (int mf = 0; mf < 4; ++mf)
#pragma unroll
        for (int nf = 0; nf < 4; ++nf)
#pragma unroll
            for (int h = 0; h < 2; ++h) {
                const int r = m0 + wm + mf * 16 + g + h * 8;
                const int c = n0 + wn + nf * 8 + 2 * tig;
                float v0 = rnd_tf32(acc[mf][nf][h * 2 + 0]);
                float v1 = rnd_tf32(acc[mf][nf][h * 2 + 1]);
                float2 out; out.x = v0; out.y = v1;
                *reinterpret_cast<float2*>(C + (size_t)r * N + c) = out;
            }

    if (bx != by) {
        __syncthreads();
        float* esm = reinterpret_cast<float*>(smraw);
#pragma unroll
        for (int mf = 0; mf < 4; ++mf)
#pragma unroll
            for (int nf = 0; nf < 4; ++nf)
#pragma unroll
                for (int h = 0; h < 2; ++h) {
                    const int rl = wm + mf * 16 + g + h * 8;
                    const int cl = wn + nf * 8 + 2 * tig;
                    esm[(cl + 0) * 132 + rl] = rnd_tf32(acc[mf][nf][h * 2 + 0]);
                    esm[(cl + 1) * 132 + rl] = rnd_tf32(acc[mf][nf][h * 2 + 1]);
                }
        __syncthreads();
#pragma unroll
        for (int ii = 0; ii < 16; ++ii) {
            const int chunk = tid + (ii << 8);
            const int row  = chunk >> 5;
            const int col4 = (chunk & 31) << 2;
            const float4 v = *reinterpret_cast<const float4*>(esm + row * 132 + col4);
            *reinterpret_cast<float4*>(C + (size_t)(n0 + row) * N + m0 + col4) = v;
        }
    }
}

// ---------------- small kernels ----------------------------------------------
__global__ void round_kernel(const float* __restrict__ in, float* __restrict__ out, int n4)
{
    int i = blockIdx.x * blockDim.x + threadIdx.x;
    if (i < n4) {
        float4 v = reinterpret_cast<const float4*>(in)[i];
        v.x = rnd_tf32(v.x); v.y = rnd_tf32(v.y);
        v.z = rnd_tf32(v.z); v.w = rnd_tf32(v.w);
        reinterpret_cast<float4*>(out)[i] = v;
    }
}

__global__ void round_and_T(const float* __restrict__ in, float* __restrict__ outR,
                            float* __restrict__ outT, int R, int C)
{
    __shared__ float tile[32][33];
    const int bx = blockIdx.x * 32, by = blockIdx.y * 32;
    const int x = threadIdx.x, y = threadIdx.y;
#pragma unroll
    for (int j = 0; j < 32; j += 8) {
        const float v = rnd_tf32(in[(size_t)(by + y + j) * C + bx + x]);
        tile[y + j][x] = v;
        outR[(size_t)(by + y + j) * C + bx + x] = v;
    }
    __syncthreads();
#pragma unroll
    for (int j = 0; j < 32; j += 8)
        outT[(size_t)(bx + y + j) * R + by + x] = tile[x][y + j];
}

__global__ void transpose_round(const float* __restrict__ in, float* __restrict__ out,
                                int R, int C)
{
    __shared__ float tile[32][33];
    const int bx = blockIdx.x * 32, by = blockIdx.y * 32;
    const int x = threadIdx.x, y = threadIdx.y;
#pragma unroll
    for (int j = 0; j < 32; j += 8)
        tile[y + j][x] = in[(size_t)(by + y + j) * C + bx + x];
    __syncthreads();
#pragma unroll
    for (int j = 0; j < 32; j += 8)
        out[(size_t)(bx + y + j) * R + by + x] = rnd_tf32(tile[x][y + j]);
}

__global__ void colsum_kernel(const float* __restrict__ in, float* __restrict__ part)
{
    int col = blockIdx.x * blockDim.x + threadIdx.x;
    int chunk = blockIdx.y;
    const float* p = in + (size_t)chunk * 128 * D_DIM + col;
    float s0 = 0.f, s1 = 0.f, s2 = 0.f, s3 = 0.f;
#pragma unroll
    for (int r = 0; r < 128; r += 4) {
        s0 += p[(size_t)(r + 0) * D_DIM];
        s1 += p[(size_t)(r + 1) * D_DIM];
        s2 += p[(size_t)(r + 2) * D_DIM];
        s3 += p[(size_t)(r + 3) * D_DIM];
    }
    part[chunk * D_DIM + col] = (s0 + s1) + (s2 + s3);
}

__global__ void creduce_kernel(const float* __restrict__ part, float* __restrict__ c)
{
    int j = blockIdx.x * blockDim.x + threadIdx.x;
    float s = 0.f;
#pragma unroll
    for (int ch = 0; ch < 32; ++ch) s += part[ch * D_DIM + j];
    c[j] = s;
}

__global__ void vecmat_kernel(const float* __restrict__ vec, const float* __restrict__ Mat,
                              float* __restrict__ outv)
{
    int j = blockIdx.x * blockDim.x + threadIdx.x;
    float s0 = 0.f, s1 = 0.f, s2 = 0.f, s3 = 0.f;
#pragma unroll 4
    for (int k = 0; k < D_DIM; k += 4) {
        s0 += vec[k + 0] * Mat[(size_t)(k + 0) * D_DIM + j];
        s1 += vec[k + 1] * Mat[(size_t)(k + 1) * D_DIM + j];
        s2 += vec[k + 2] * Mat[(size_t)(k + 2) * D_DIM + j];
        s3 += vec[k + 3] * Mat[(size_t)(k + 3) * D_DIM + j];
    }
    outv[j] = (s0 + s1) + (s2 + s3);
}

__global__ void bn_kernel(const float* __restrict__ Mm, const float* __restrict__ c,
                          const float* __restrict__ b, const float* __restrict__ lrb,
                          float* __restrict__ bn, float coef)
{
    int j = blockIdx.x * blockDim.x + threadIdx.x;
    float s0 = 0.f, s1 = 0.f, s2 = 0.f, s3 = 0.f;
#pragma unroll 4
    for (int k = 0; k < D_DIM; k += 4) {
        s0 += c[k + 0] * Mm[(size_t)(k + 0) * D_DIM + j];
        s1 += c[k + 1] * Mm[(size_t)(k + 1) * D_DIM + j];
        s2 += c[k + 2] * Mm[(size_t)(k + 2) * D_DIM + j];
        s3 += c[k + 3] * Mm[(size_t)(k + 3) * D_DIM + j];
    }
    float s = (s0 + s1) + (s2 + s3);
    bn[j] = b[j] - lrb[j] * coef * (s + (float)B_TOK * b[j]);
}

// ---------------- host --------------------------------------------------------
extern "C" void kernel_launch(void* const* d_in, const int* in_sizes, int n_in,
                              void* d_out, int out_size)
{
    const float* src  = (const float*)d_in[0];
    const float* th_k = (const float*)d_in[1];
    const float* th_q = (const float*)d_in[2];
    const float* th_v = (const float*)d_in[3];
    const float* W    = (const float*)d_in[4];
    const float* b    = (const float*)d_in[5];
    const float* lr_w = (const float*)d_in[6];
    const float* lr_b = (const float*)d_in[7];
    float* out = (float*)d_out;

    float *srcR, *srcT, *thkR, *thqR, *WR, *thkT, *S, *Mm, *T1, *MT, *T1T, *Wn, *P, *PT;
    float *part, *cvec, *vvec, *bn;
    cudaGetSymbolAddress((void**)&srcR, g_srcR);
    cudaGetSymbolAddress((void**)&srcT, g_srcT);
    cudaGetSymbolAddress((void**)&thkR, g_thkR);
    cudaGetSymbolAddress((void**)&thqR, g_thqR);
    cudaGetSymbolAddress((void**)&WR,   g_WR);
    cudaGetSymbolAddress((void**)&thkT, g_thkT);
    cudaGetSymbolAddress((void**)&S,    g_S);
    cudaGetSymbolAddress((void**)&Mm,   g_M);
    cudaGetSymbolAddress((void**)&T1,   g_T1);
    cudaGetSymbolAddress((void**)&MT,   g_MT);
    cudaGetSymbolAddress((void**)&T1T,  g_T1T);
    cudaGetSymbolAddress((void**)&Wn,   g_Wn);
    cudaGetSymbolAddress((void**)&P,    g_P);
    cudaGetSymbolAddress((void**)&PT,   g_PT);
    cudaGetSymbolAddress((void**)&part, g_part);
    cudaGetSymbolAddress((void**)&cvec, g_c);
    cudaGetSymbolAddress((void**)&vvec, g_v);
    cudaGetSymbolAddress((void**)&bn,   g_bn);

    const float coef = 2.0f / ((float)B_TOK * (float)D_DIM);
    const int SMEM_W = 4 * (128 + 256) * 32 * 4;   // 196608 (wide kernel)
    const int SMEM_S = 4 * 2 * 128 * 32 * 4;       // 131072 (sym kernel)

    cudaFuncSetAttribute(ntgemm2<0, false>, cudaFuncAttributeMaxDynamicSharedMemorySize, SMEM_W);
    cudaFuncSetAttribute(ntgemm2<1, true >, cudaFuncAttributeMaxDynamicSharedMemorySize, SMEM_W);
    cudaFuncSetAttribute(ntgemm2<2, true >, cudaFuncAttributeMaxDynamicSharedMemorySize, SMEM_W);
    cudaFuncSetAttribute(ntgemm2<3, false>, cudaFuncAttributeMaxDynamicSharedMemorySize, SMEM_W);
    cudaFuncSetAttribute(ntgemm2<4, false>, cudaFuncAttributeMaxDynamicSharedMemorySize, SMEM_W);
    cudaFuncSetAttribute(symgemm,           cudaFuncAttributeMaxDynamicSharedMemorySize, SMEM_S);

    dim3 tb(32, 8);
    dim3 gridW(D_DIM / 256, D_DIM / 128);   // (8, 16) = 128 CTAs
    dim3 gridZ(D_DIM / 256, B_TOK / 128);   // (8, 32) = 256 CTAs
    const int nSymTiles = (D_DIM / 128) * (D_DIM / 128 + 1) / 2;   // 136

    // launches 1-5 (prep), #6 = M-GEMM (ncu -s 5 profiles this one)
    round_and_T<<<dim3(D_DIM / 32, B_TOK / 32), tb>>>(src, srcR, srcT, B_TOK, D_DIM);   // 1
    round_and_T<<<dim3(D_DIM / 32, D_DIM / 32), tb>>>(th_k, thkR, thkT, D_DIM, D_DIM);  // 2
    round_kernel<<<(D_DIM * D_DIM / 4 + 255) / 256, 256>>>(th_q, thqR, D_DIM * D_DIM / 4); // 3
    round_kernel<<<(D_DIM * D_DIM / 4 + 255) / 256, 256>>>(W, WR, D_DIM * D_DIM / 4);      // 4
    colsum_kernel<<<dim3(D_DIM / 256, 32), 256>>>(src, part);                               // 5

    // 6: M = theta_k @ W^T + theta_k - theta_v   (PROFILED)
    ntgemm2<1, true ><<<gridW, 256, SMEM_W>>>(thkR, WR, Mm, D_DIM, D_DIM, D_DIM,
                                              nullptr, th_k, th_v, nullptr, nullptr, 0.f);

    // S = src^T @ src  (symmetric)
    symgemm<<<nSymTiles, 256, SMEM_S>>>(srcT, S, D_DIM, B_TOK);

    creduce_kernel<<<D_DIM / 256, 256>>>(part, cvec);
    vecmat_kernel<<<D_DIM / 128, 128>>>(cvec, th_k, vvec);

    // T1 = S @ theta_k
    ntgemm2<0, false><<<gridW, 256, SMEM_W>>>(S, thkT, T1, D_DIM, D_DIM, D_DIM,
                                              nullptr, nullptr, nullptr, nullptr, nullptr, 0.f);
    transpose_round<<<dim3(D_DIM / 32, D_DIM / 32), tb>>>(Mm, MT, D_DIM, D_DIM);
    transpose_round<<<dim3(D_DIM / 32, D_DIM / 32), tb>>>(T1, T1T, D_DIM, D_DIM);

    // Wn = W - lr_w * coef * (M^T @ T1 + b (x) v)
    ntgemm2<2, true ><<<gridW, 256, SMEM_W>>>(MT, T1T, Wn, D_DIM, D_DIM, D_DIM,
                                              nullptr, W, lr_w, b, vvec, coef);
    bn_kernel<<<D_DIM / 128, 128>>>(Mm, cvec, b, lr_b, bn, coef);

    // P = theta_q @ Wn^T + theta_q
    ntgemm2<3, false><<<gridW, 256, SMEM_W>>>(thqR, Wn, P, D_DIM, D_DIM, D_DIM,
                                              nullptr, th_q, nullptr, nullptr, nullptr, 0.f);
    transpose_round<<<dim3(D_DIM / 32, D_DIM / 32), tb>>>(P, PT, D_DIM, D_DIM);

    // z = src @ P + bn
    ntgemm2<4, false><<<gridZ, 256, SMEM_W>>>(srcR, PT, out, B_TOK, D_DIM, D_DIM,
                                              bn, nullptr, nullptr, nullptr, nullptr, 0.f);
}

// round 9
// speedup vs baseline: 1.0485x; 1.0485x over previous
#include <cuda_runtime.h>
#include <cstdint>
#include <math.h>

#define D_DIM 2048
#define B_TOK 4096

// ---------------- scratch (device globals; no allocation allowed) ----------
__device__ float g_srcR[(size_t)B_TOK * D_DIM];
__device__ float g_srcT[(size_t)B_TOK * D_DIM];
__device__ float g_thkR[(size_t)D_DIM * D_DIM];
__device__ float g_thqR[(size_t)D_DIM * D_DIM];
__device__ float g_WR  [(size_t)D_DIM * D_DIM];
__device__ float g_thkT[(size_t)D_DIM * D_DIM];
__device__ float g_S   [(size_t)D_DIM * D_DIM];
__device__ float g_M   [(size_t)D_DIM * D_DIM];
__device__ float g_MT  [(size_t)D_DIM * D_DIM];
__device__ float g_T1T [(size_t)D_DIM * D_DIM];
__device__ float g_Wn  [(size_t)D_DIM * D_DIM];
__device__ float g_PT  [(size_t)D_DIM * D_DIM];
__device__ float g_part[32 * D_DIM];
__device__ float g_c   [D_DIM];
__device__ float g_v   [D_DIM];
__device__ float g_bn  [D_DIM];

// ---------------- PTX helpers ----------------------------------------------
__device__ __forceinline__ float rnd_tf32(float x) {
    uint32_t r;
    asm("cvt.rna.tf32.f32 %0, %1;" : "=r"(r) : "f"(x));
    return __uint_as_float(r);
}

__device__ __forceinline__ void cp16(uint32_t dst, const float* src) {
    asm volatile("cp.async.cg.shared.global [%0], [%1], 16;" :: "r"(dst), "l"(src));
}

__device__ __forceinline__ void ldsm4(uint32_t& r0, uint32_t& r1, uint32_t& r2, uint32_t& r3,
                                      uint32_t addr) {
    asm volatile("ldmatrix.sync.aligned.m8n8.x4.shared.b16 {%0,%1,%2,%3}, [%4];"
                 : "=r"(r0), "=r"(r1), "=r"(r2), "=r"(r3) : "r"(addr));
}

__device__ __forceinline__ void mma_tf32(float c[4], const uint32_t a[4],
                                         uint32_t b0, uint32_t b1) {
    asm volatile(
        "mma.sync.aligned.m16n8k8.row.col.f32.tf32.tf32.f32 "
        "{%0,%1,%2,%3}, {%4,%5,%6,%7}, {%8,%9}, {%0,%1,%2,%3};"
        : "+f"(c[0]), "+f"(c[1]), "+f"(c[2]), "+f"(c[3])
        : "r"(a[0]), "r"(a[1]), "r"(a[2]), "r"(a[3]), "r"(b0), "r"(b1));
}

// ---------------------------------------------------------------------------
// 4-warp NT tf32 GEMM: C[M,N] = A[M,K]*B[N,K]^T. CTA 128x128, 4 warps of
// 64x64, BK=32, 3-stage cp.async (96KB, 2 CTAs/SM). Inputs pre-rounded tf32.
// Safe pipeline: wait_group -> syncthreads -> loadTile(t+2).
// EPI 0: v = acc
// EPI 1: v = acc + e1[idx] - e2[idx]
// EPI 2: v = e1[idx] - e2[idx] * coef * (acc + ev0[row]*ev1[col])
// EPI 3: v = acc + e1[idx]
// EPI 4: v = acc + e0[col]
// TW 0: write C only.  TW 1: write C and CT (=C^T).  TW 2: write CT only.
// ---------------------------------------------------------------------------
template <int EPI, bool RND, int TW>
__global__ void __launch_bounds__(128, 2)
ntgemm3(const float* __restrict__ A, const float* __restrict__ B,
        float* __restrict__ C, float* __restrict__ CT, int M, int N, int K,
        const float* __restrict__ e0, const float* __restrict__ e1,
        const float* __restrict__ e2, const float* __restrict__ ev0,
        const float* __restrict__ ev1, float coef)
{
    constexpr int BK   = 32;
    constexpr int TILE = 128 * BK * 4;   // 16 KB per operand
    constexpr int SS   = 2 * TILE;       // 32 KB per stage

    extern __shared__ __align__(128) char smraw[];
    const uint32_t sb = (uint32_t)__cvta_generic_to_shared(smraw);

    const int tid  = threadIdx.x;        // 0..127
    const int lane = tid & 31;
    const int wid  = tid >> 5;           // 0..3
    const int wm   = (wid & 1) * 64;
    const int wn   = (wid >> 1) * 64;
    const int m0   = blockIdx.y * 128;
    const int n0   = blockIdx.x * 128;

    // loader: 16 rows x 8 chunks per pass, 8 passes each for A and B
    const int lr = tid >> 3;             // 0..15
    const int lc = tid & 7;
    const uint32_t lOff = (uint32_t)(lr * 128 + ((lc ^ (lr & 7)) << 4));
    const float* aG = A + (size_t)(m0 + lr) * K + lc * 4;
    const float* bG = B + (size_t)(n0 + lr) * K + lc * 4;

    auto loadTile = [&](int t) {
        const uint32_t base = sb + (uint32_t)((t % 3) * SS);
        const float* a = aG + (size_t)t * BK;
        const float* b = bG + (size_t)t * BK;
#pragma unroll
        for (int i = 0; i < 8; ++i)
            cp16(base + lOff + 2048u * i, a + (size_t)(16 * i) * K);
#pragma unroll
        for (int i = 0; i < 8; ++i)
            cp16(base + TILE + lOff + 2048u * i, b + (size_t)(16 * i) * K);
        asm volatile("cp.async.commit_group;" ::: "memory");
    };

    const int rr  = lane & 7;
    const int loA = (lane >> 3) & 1;
    const int hiA = (lane >> 4) & 1;
    const int loB = (lane >> 4) & 1;
    const int hiB = (lane >> 3) & 1;
    const uint32_t swz = (uint32_t)rr << 4;

    uint32_t aRow[4], bRow[4];
#pragma unroll
    for (int mf = 0; mf < 4; ++mf)
        aRow[mf] = (uint32_t)((wm + mf * 16 + loA * 8 + rr) * 128);
#pragma unroll
    for (int nfp = 0; nfp < 4; ++nfp)
        bRow[nfp] = (uint32_t)((wn + nfp * 16 + loB * 8 + rr) * 128);

    float acc[4][8][4];
#pragma unroll
    for (int i = 0; i < 4; ++i)
#pragma unroll
        for (int j = 0; j < 8; ++j)
#pragma unroll
            for (int k = 0; k < 4; ++k) acc[i][j][k] = 0.0f;

    const int nt = K / BK;
    loadTile(0);
    loadTile(1);

    for (int t = 0; t < nt; ++t) {
        if (t + 1 < nt) asm volatile("cp.async.wait_group 1;" ::: "memory");
        else            asm volatile("cp.async.wait_group 0;" ::: "memory");
        __syncthreads();
        if (t + 2 < nt) loadTile(t + 2);   // stage (t+2)%3 == (t-1)%3, consumed

        const uint32_t stA = sb + (uint32_t)((t % 3) * SS);
        const uint32_t stB = stA + TILE;

#pragma unroll
        for (int kk = 0; kk < 4; ++kk) {
            const uint32_t ak = (((uint32_t)(2 * kk + hiA)) << 4) ^ swz;
            const uint32_t bk = (((uint32_t)(2 * kk + hiB)) << 4) ^ swz;
            uint32_t af[4][4];
#pragma unroll
            for (int mf = 0; mf < 4; ++mf)
                ldsm4(af[mf][0], af[mf][1], af[mf][2], af[mf][3], stA + aRow[mf] + ak);
            uint32_t bf[4][4];
#pragma unroll
            for (int nfp = 0; nfp < 4; ++nfp)
                ldsm4(bf[nfp][0], bf[nfp][1], bf[nfp][2], bf[nfp][3], stB + bRow[nfp] + bk);
#pragma unroll
            for (int mf = 0; mf < 4; ++mf)
#pragma unroll
                for (int nf = 0; nf < 8; ++nf)
                    mma_tf32(acc[mf][nf], af[mf],
                             bf[nf >> 1][(nf & 1) * 2], bf[nf >> 1][(nf & 1) * 2 + 1]);
        }
    }

    // ---- epilogue ----
    const int g   = lane >> 2;
    const int tig = lane & 3;
    float* esm = reinterpret_cast<float*>(smraw);
    if (TW) __syncthreads();   // mainloop smem reads done before staging reuse

#pragma unroll
    for (int mf = 0; mf < 4; ++mf) {
#pragma unroll
        for (int nf = 0; nf < 8; ++nf) {
#pragma unroll
            for (int h = 0; h < 2; ++h) {
                const int rl = wm + mf * 16 + g + h * 8;
                const int cl = wn + nf * 8 + 2 * tig;
                const int r = m0 + rl;
                const int c = n0 + cl;
                const size_t idx = (size_t)r * N + c;
                float v0 = acc[mf][nf][h * 2 + 0];
                float v1 = acc[mf][nf][h * 2 + 1];
                if (EPI == 1) {
                    const float2 a1 = *reinterpret_cast<const float2*>(e1 + idx);
                    const float2 a2 = *reinterpret_cast<const float2*>(e2 + idx);
                    v0 += a1.x - a2.x;
                    v1 += a1.y - a2.y;
                } else if (EPI == 2) {
                    const float2 w  = *reinterpret_cast<const float2*>(e1 + idx);
                    const float2 lr = *reinterpret_cast<const float2*>(e2 + idx);
                    const float bi  = ev0[r];
                    const float g0  = coef * (v0 + bi * ev1[c]);
                    const float g1  = coef * (v1 + bi * ev1[c + 1]);
                    v0 = w.x - lr.x * g0;
                    v1 = w.y - lr.y * g1;
                } else if (EPI == 3) {
                    const float2 a1 = *reinterpret_cast<const float2*>(e1 + idx);
                    v0 += a1.x;
                    v1 += a1.y;
                } else if (EPI == 4) {
                    v0 += e0[c];
                    v1 += e0[c + 1];
                }
                if (RND) { v0 = rnd_tf32(v0); v1 = rnd_tf32(v1); }
                if (TW != 2) {
                    float2 out; out.x = v0; out.y = v1;
                    *reinterpret_cast<float2*>(C + idx) = out;
                }
                if (TW) {
                    esm[(cl + 0) * 132 + rl] = v0;
                    esm[(cl + 1) * 132 + rl] = v1;
                }
            }
        }
    }

    if (TW) {
        __syncthreads();
#pragma unroll
        for (int i = 0; i < 32; ++i) {
            const int chunk = tid + (i << 7);
            const int row  = chunk >> 5;          // 0..127 (col of C)
            const int col4 = (chunk & 31) << 2;   // 0..124 (row of C)
            const float4 v = *reinterpret_cast<const float4*>(esm + row * 132 + col4);
            *reinterpret_cast<float4*>(CT + (size_t)(n0 + row) * M + m0 + col4) = v;
        }
    }
}

// ---------------------------------------------------------------------------
// Symmetric Gram GEMM (proven in R8): CTA 128x128, 8 warps, 4-stage, safe.
// ---------------------------------------------------------------------------
__global__ void __launch_bounds__(256, 1)
symgemm(const float* __restrict__ A, float* __restrict__ C, int N, int K)
{
    constexpr int BK   = 32;
    constexpr int TILE = 128 * BK * 4;
    constexpr int SS   = 2 * TILE;

    extern __shared__ __align__(128) char smraw[];
    const uint32_t sb = (uint32_t)__cvta_generic_to_shared(smraw);

    const int tid  = threadIdx.x;
    const int lane = tid & 31;
    const int wid  = tid >> 5;
    const int wm   = (wid & 1) * 64;
    const int wn   = (wid >> 1) * 32;

    const int i = blockIdx.x;
    int e = (int)((sqrtf(8.0f * (float)i + 1.0f) - 1.0f) * 0.5f);
    while ((e + 1) * (e + 2) / 2 <= i) ++e;
    while (e * (e + 1) / 2 > i) --e;
    const int by = e;
    const int bx = i - e * (e + 1) / 2;
    const int m0 = by * 128;
    const int n0 = bx * 128;

    const int lr = tid >> 3;
    const int lc = tid & 7;
    const uint32_t lOff = (uint32_t)(lr * 128 + ((lc ^ (lr & 7)) << 4));
    const float* aG = A + (size_t)(m0 + lr) * K + lc * 4;
    const float* bG = A + (size_t)(n0 + lr) * K + lc * 4;

    auto loadTile = [&](int t) {
        const uint32_t base = sb + (uint32_t)((t & 3) * SS);
        const float* a = aG + (size_t)t * BK;
        const float* b = bG + (size_t)t * BK;
#pragma unroll
        for (int ii = 0; ii < 4; ++ii)
            cp16(base + lOff + 4096u * ii, a + (size_t)(32 * ii) * K);
#pragma unroll
        for (int ii = 0; ii < 4; ++ii)
            cp16(base + TILE + lOff + 4096u * ii, b + (size_t)(32 * ii) * K);
        asm volatile("cp.async.commit_group;" ::: "memory");
    };

    const int rr  = lane & 7;
    const int loA = (lane >> 3) & 1;
    const int hiA = (lane >> 4) & 1;
    const int loB = (lane >> 4) & 1;
    const int hiB = (lane >> 3) & 1;
    const uint32_t swz = (uint32_t)rr << 4;

    uint32_t aRow[4], bRow[2];
#pragma unroll
    for (int mf = 0; mf < 4; ++mf)
        aRow[mf] = (uint32_t)((wm + mf * 16 + loA * 8 + rr) * 128);
#pragma unroll
    for (int nfp = 0; nfp < 2; ++nfp)
        bRow[nfp] = (uint32_t)((wn + nfp * 16 + loB * 8 + rr) * 128);

    float acc[4][4][4];
#pragma unroll
    for (int a = 0; a < 4; ++a)
#pragma unroll
        for (int b = 0; b < 4; ++b)
#pragma unroll
            for (int k = 0; k < 4; ++k) acc[a][b][k] = 0.0f;

    const int nt = K / BK;
    loadTile(0); loadTile(1); loadTile(2);

    for (int t = 0; t < nt; ++t) {
        if (t + 2 < nt)      asm volatile("cp.async.wait_group 2;" ::: "memory");
        else if (t + 1 < nt) asm volatile("cp.async.wait_group 1;" ::: "memory");
        else                 asm volatile("cp.async.wait_group 0;" ::: "memory");
        __syncthreads();
        if (t + 3 < nt) loadTile(t + 3);

        const uint32_t stA = sb + (uint32_t)((t & 3) * SS);
        const uint32_t stB = stA + TILE;

#pragma unroll
        for (int kk = 0; kk < 4; ++kk) {
            const uint32_t ak = (((uint32_t)(2 * kk + hiA)) << 4) ^ swz;
            const uint32_t bk = (((uint32_t)(2 * kk + hiB)) << 4) ^ swz;
            uint32_t af[4][4];
#pragma unroll
            for (int mf = 0; mf < 4; ++mf)
                ldsm4(af[mf][0], af[mf][1], af[mf][2], af[mf][3], stA + aRow[mf] + ak);
            uint32_t bf[2][4];
#pragma unroll
            for (int nfp = 0; nfp < 2; ++nfp)
                ldsm4(bf[nfp][0], bf[nfp][1], bf[nfp][2], bf[nfp][3], stB + bRow[nfp] + bk);
#pragma unroll
            for (int mf = 0; mf < 4; ++mf)
#pragma unroll
                for (int nf = 0; nf < 4; ++nf)
                    mma_tf32(acc[mf][nf], af[mf],
                             bf[nf >> 1][(nf & 1) * 2], bf[nf >> 1][(nf & 1) * 2 + 1]);
        }
    }

    const int g   = lane >> 2;
    const int tig = lane & 3;
#pragma unroll
    for (int mf = 0; mf < 4; ++mf)
#pragma unroll
        for (int nf = 0; nf < 4; ++nf)
#pragma unroll
            for (int h = 0; h < 2; ++h) {
                const int r = m0 + wm + mf * 16 + g + h * 8;
                const int c = n0 + wn + nf * 8 + 2 * tig;
                float v0 = rnd_tf32(acc[mf][nf][h * 2 + 0]);
                float v1 = rnd_tf32(acc[mf][nf][h * 2 + 1]);
                float2 out; out.x = v0; out.y = v1;
                *reinterpret_cast<float2*>(C + (size_t)r * N + c) = out;
            }

    if (bx != by) {
        __syncthreads();
        float* esm = reinterpret_cast<float*>(smraw);
#pragma unroll
        for (int mf = 0; mf < 4; ++mf)
#pragma unroll
            for (int nf = 0; nf < 4; ++nf)
#pragma unroll
                for (int h = 0; h < 2; ++h) {
                    const int rl = wm + mf * 16 + g + h * 8;
                    const int cl = wn + nf * 8 + 2 * tig;
                    esm[(cl + 0) * 132 + rl] = rnd_tf32(acc[mf][nf][h * 2 + 0]);
                    esm[(cl + 1) * 132 + rl] = rnd_tf32(acc[mf][nf][h * 2 + 1]);
                }
        __syncthreads();
#pragma unroll
        for (int ii = 0; ii < 16; ++ii) {
            const int chunk = tid + (ii << 8);
            const int row  = chunk >> 5;
            const int col4 = (chunk & 31) << 2;
            const float4 v = *reinterpret_cast<const float4*>(esm + row * 132 + col4);
            *reinterpret_cast<float4*>(C + (size_t)(n0 + row) * N + m0 + col4) = v;
        }
    }
}

// ---------------- small kernels ----------------------------------------------
__global__ void round_kernel(const float* __restrict__ in, float* __restrict__ out, int n4)
{
    int i = blockIdx.x * blockDim.x + threadIdx.x;
    if (i < n4) {
        float4 v = reinterpret_cast<const float4*>(in)[i];
        v.x = rnd_tf32(v.x); v.y = rnd_tf32(v.y);
        v.z = rnd_tf32(v.z); v.w = rnd_tf32(v.w);
        reinterpret_cast<float4*>(out)[i] = v;
    }
}

__global__ void round_and_T(const float* __restrict__ in, float* __restrict__ outR,
                            float* __restrict__ outT, int R, int C)
{
    __shared__ float tile[32][33];
    const int bx = blockIdx.x * 32, by = blockIdx.y * 32;
    const int x = threadIdx.x, y = threadIdx.y;
#pragma unroll
    for (int j = 0; j < 32; j += 8) {
        const float v = rnd_tf32(in[(size_t)(by + y + j) * C + bx + x]);
        tile[y + j][x] = v;
        outR[(size_t)(by + y + j) * C + bx + x] = v;
    }
    __syncthreads();
#pragma unroll
    for (int j = 0; j < 32; j += 8)
        outT[(size_t)(bx + y + j) * R + by + x] = tile[x][y + j];
}

__global__ void colsum_kernel(const float* __restrict__ in, float* __restrict__ part)
{
    int col = blockIdx.x * blockDim.x + threadIdx.x;
    int chunk = blockIdx.y;
    const float* p = in + (size_t)chunk * 128 * D_DIM + col;
    float s0 = 0.f, s1 = 0.f, s2 = 0.f, s3 = 0.f;
#pragma unroll
    for (int r = 0; r < 128; r += 4) {
        s0 += p[(size_t)(r + 0) * D_DIM];
        s1 += p[(size_t)(r + 1) * D_DIM];
        s2 += p[(size_t)(r + 2) * D_DIM];
        s3 += p[(size_t)(r + 3) * D_DIM];
    }
    part[chunk * D_DIM + col] = (s0 + s1) + (s2 + s3);
}

__global__ void creduce_kernel(const float* __restrict__ part, float* __restrict__ c)
{
    int j = blockIdx.x * blockDim.x + threadIdx.x;
    float s = 0.f;
#pragma unroll
    for (int ch = 0; ch < 32; ++ch) s += part[ch * D_DIM + j];
    c[j] = s;
}

__global__ void vecmat_kernel(const float* __restrict__ vec, const float* __restrict__ Mat,
                              float* __restrict__ outv)
{
    int j = blockIdx.x * blockDim.x + threadIdx.x;
    float s0 = 0.f, s1 = 0.f, s2 = 0.f, s3 = 0.f;
#pragma unroll 4
    for (int k = 0; k < D_DIM; k += 4) {
        s0 += vec[k + 0] * Mat[(size_t)(k + 0) * D_DIM + j];
        s1 += vec[k + 1] * Mat[(size_t)(k + 1) * D_DIM + j];
        s2 += vec[k + 2] * Mat[(size_t)(k + 2) * D_DIM + j];
        s3 += vec[k + 3] * Mat[(size_t)(k + 3) * D_DIM + j];
    }
    outv[j] = (s0 + s1) + (s2 + s3);
}

__global__ void bn_kernel(const float* __restrict__ Mm, const float* __restrict__ c,
                          const float* __restrict__ b, const float* __restrict__ lrb,
                          float* __restrict__ bn, float coef)
{
    int j = blockIdx.x * blockDim.x + threadIdx.x;
    float s0 = 0.f, s1 = 0.f, s2 = 0.f, s3 = 0.f;
#pragma unroll 4
    for (int k = 0; k < D_DIM; k += 4) {
        s0 += c[k + 0] * Mm[(size_t)(k + 0) * D_DIM + j];
        s1 += c[k + 1] * Mm[(size_t)(k + 1) * D_DIM + j];
        s2 += c[k + 2] * Mm[(size_t)(k + 2) * D_DIM + j];
        s3 += c[k + 3] * Mm[(size_t)(k + 3) * D_DIM + j];
    }
    float s = (s0 + s1) + (s2 + s3);
    bn[j] = b[j] - lrb[j] * coef * (s + (float)B_TOK * b[j]);
}

// ---------------- host --------------------------------------------------------
extern "C" void kernel_launch(void* const* d_in, const int* in_sizes, int n_in,
                              void* d_out, int out_size)
{
    const float* src  = (const float*)d_in[0];
    const float* th_k = (const float*)d_in[1];
    const float* th_q = (const float*)d_in[2];
    const float* th_v = (const float*)d_in[3];
    const float* W    = (const float*)d_in[4];
    const float* b    = (const float*)d_in[5];
    const float* lr_w = (const float*)d_in[6];
    const float* lr_b = (const float*)d_in[7];
    float* out = (float*)d_out;

    float *srcR, *srcT, *thkR, *thqR, *WR, *thkT, *S, *Mm, *MT, *T1T, *Wn, *PT;
    float *part, *cvec, *vvec, *bn;
    cudaGetSymbolAddress((void**)&srcR, g_srcR);
    cudaGetSymbolAddress((void**)&srcT, g_srcT);
    cudaGetSymbolAddress((void**)&thkR, g_thkR);
    cudaGetSymbolAddress((void**)&thqR, g_thqR);
    cudaGetSymbolAddress((void**)&WR,   g_WR);
    cudaGetSymbolAddress((void**)&thkT, g_thkT);
    cudaGetSymbolAddress((void**)&S,    g_S);
    cudaGetSymbolAddress((void**)&Mm,   g_M);
    cudaGetSymbolAddress((void**)&MT,   g_MT);
    cudaGetSymbolAddress((void**)&T1T,  g_T1T);
    cudaGetSymbolAddress((void**)&Wn,   g_Wn);
    cudaGetSymbolAddress((void**)&PT,   g_PT);
    cudaGetSymbolAddress((void**)&part, g_part);
    cudaGetSymbolAddress((void**)&cvec, g_c);
    cudaGetSymbolAddress((void**)&vvec, g_v);
    cudaGetSymbolAddress((void**)&bn,   g_bn);

    const float coef = 2.0f / ((float)B_TOK * (float)D_DIM);
    const int SMEM3 = 3 * 2 * 128 * 32 * 4;    // 98304 (4-warp kernel, 3 stages)
    const int SMEM_S = 4 * 2 * 128 * 32 * 4;   // 131072 (sym kernel)

    cudaFuncSetAttribute(ntgemm3<1, true,  1>, cudaFuncAttributeMaxDynamicSharedMemorySize, SMEM3);
    cudaFuncSetAttribute(ntgemm3<0, false, 2>, cudaFuncAttributeMaxDynamicSharedMemorySize, SMEM3);
    cudaFuncSetAttribute(ntgemm3<2, true,  0>, cudaFuncAttributeMaxDynamicSharedMemorySize, SMEM3);
    cudaFuncSetAttribute(ntgemm3<3, false, 2>, cudaFuncAttributeMaxDynamicSharedMemorySize, SMEM3);
    cudaFuncSetAttribute(ntgemm3<4, false, 0>, cudaFuncAttributeMaxDynamicSharedMemorySize, SMEM3);
    cudaFuncSetAttribute(symgemm,              cudaFuncAttributeMaxDynamicSharedMemorySize, SMEM_S);

    dim3 tb(32, 8);
    dim3 gridD(D_DIM / 128, D_DIM / 128);   // (16, 16) = 256 CTAs
    dim3 gridZ(D_DIM / 128, B_TOK / 128);   // (16, 32) = 512 CTAs
    const int nSymTiles = (D_DIM / 128) * (D_DIM / 128 + 1) / 2;   // 136

    // 1-3: prep needed by M-GEMM
    round_and_T<<<dim3(D_DIM / 32, B_TOK / 32), tb>>>(src, srcR, srcT, B_TOK, D_DIM);
    round_and_T<<<dim3(D_DIM / 32, D_DIM / 32), tb>>>(th_k, thkR, thkT, D_DIM, D_DIM);
    round_kernel<<<(D_DIM * D_DIM / 4 + 255) / 256, 256>>>(W, WR, D_DIM * D_DIM / 4);

    // 4: M = theta_k @ W^T + theta_k - theta_v  -> Mm and MT  (PROFILED SLOT)
    ntgemm3<1, true,  1><<<gridD, 128, SMEM3>>>(thkR, WR, Mm, MT, D_DIM, D_DIM, D_DIM,
                                                nullptr, th_k, th_v, nullptr, nullptr, 0.f);

    // remaining prep
    round_kernel<<<(D_DIM * D_DIM / 4 + 255) / 256, 256>>>(th_q, thqR, D_DIM * D_DIM / 4);
    colsum_kernel<<<dim3(D_DIM / 256, 32), 256>>>(src, part);

    // S = src^T @ src (symmetric)
    symgemm<<<nSymTiles, 256, SMEM_S>>>(srcT, S, D_DIM, B_TOK);

    creduce_kernel<<<D_DIM / 256, 256>>>(part, cvec);
    vecmat_kernel<<<D_DIM / 128, 128>>>(cvec, th_k, vvec);

    // T1T = (S @ theta_k)^T  (transpose-only epilogue)
    ntgemm3<0, false, 2><<<gridD, 128, SMEM3>>>(S, thkT, nullptr, T1T, D_DIM, D_DIM, D_DIM,
                                                nullptr, nullptr, nullptr, nullptr, nullptr, 0.f);

    // Wn = W - lr_w * coef * (M^T @ T1 + b (x) v)
    ntgemm3<2, true,  0><<<gridD, 128, SMEM3>>>(MT, T1T, Wn, nullptr, D_DIM, D_DIM, D_DIM,
                                                nullptr, W, lr_w, b, vvec, coef);
    bn_kernel<<<D_DIM / 128, 128>>>(Mm, cvec, b, lr_b, bn, coef);

    // PT = (theta_q @ Wn^T + theta_q)^T  (transpose-only epilogue)
    ntgemm3<3, false, 2><<<gridD, 128, SMEM3>>>(thqR, Wn, nullptr, PT, D_DIM, D_DIM, D_DIM,
                                                nullptr, th_q, nullptr, nullptr, nullptr, 0.f);

    // z = src @ P + bn  (NT with PT)
    ntgemm3<4, false, 0><<<gridZ, 128, SMEM3>>>(srcR, PT, out, nullptr, B_TOK, D_DIM, D_DIM,
                                                bn, nullptr, nullptr, nullptr, nullptr, 0.f);
}

// round 10
// speedup vs baseline: 1.0515x; 1.0029x over previous
#include <cuda_runtime.h>
#include <cstdint>
#include <math.h>

#define D_DIM 2048
#define B_TOK 4096

// ---------------- scratch (device globals; no allocation allowed) ----------
__device__ float g_srcR[(size_t)B_TOK * D_DIM];
__device__ float g_srcT[(size_t)B_TOK * D_DIM];
__device__ float g_thkR[(size_t)D_DIM * D_DIM];
__device__ float g_thqR[(size_t)D_DIM * D_DIM];
__device__ float g_WR  [(size_t)D_DIM * D_DIM];
__device__ float g_thkT[(size_t)D_DIM * D_DIM];
__device__ float g_S   [(size_t)D_DIM * D_DIM];
__device__ float g_M   [(size_t)D_DIM * D_DIM];
__device__ float g_MT  [(size_t)D_DIM * D_DIM];
__device__ float g_T1T [(size_t)D_DIM * D_DIM];
__device__ float g_Wn  [(size_t)D_DIM * D_DIM];
__device__ float g_PT  [(size_t)D_DIM * D_DIM];
__device__ float g_part[32 * D_DIM];
__device__ float g_c   [D_DIM];
__device__ float g_v   [D_DIM];
__device__ float g_bn  [D_DIM];

// ---------------- PTX helpers ----------------------------------------------
__device__ __forceinline__ float rnd_tf32(float x) {
    uint32_t r;
    asm("cvt.rna.tf32.f32 %0, %1;" : "=r"(r) : "f"(x));
    return __uint_as_float(r);
}

__device__ __forceinline__ void cp16(uint32_t dst, const float* src) {
    asm volatile("cp.async.cg.shared.global [%0], [%1], 16;" :: "r"(dst), "l"(src));
}

__device__ __forceinline__ void ldsm4(uint32_t& r0, uint32_t& r1, uint32_t& r2, uint32_t& r3,
                                      uint32_t addr) {
    asm volatile("ldmatrix.sync.aligned.m8n8.x4.shared.b16 {%0,%1,%2,%3}, [%4];"
                 : "=r"(r0), "=r"(r1), "=r"(r2), "=r"(r3) : "r"(addr));
}

__device__ __forceinline__ void mma_tf32(float c[4], const uint32_t a[4],
                                         uint32_t b0, uint32_t b1) {
    asm volatile(
        "mma.sync.aligned.m16n8k8.row.col.f32.tf32.tf32.f32 "
        "{%0,%1,%2,%3}, {%4,%5,%6,%7}, {%8,%9}, {%0,%1,%2,%3};"
        : "+f"(c[0]), "+f"(c[1]), "+f"(c[2]), "+f"(c[3])
        : "r"(a[0]), "r"(a[1]), "r"(a[2]), "r"(a[3]), "r"(b0), "r"(b1));
}

// ---------------------------------------------------------------------------
// 4-warp NT tf32 GEMM: C[M,N] = A[M,K]*B[N,K]^T. CTA 128x128, 4 warps of
// 64x64, BK=32, 3-stage cp.async (96KB, 2 CTAs/SM). Inputs pre-rounded tf32.
// Safe pipeline: wait_group -> syncthreads -> loadTile(t+2).
// EPI 0: v = acc
// EPI 1: v = acc + e1[idx] - e2[idx]
// EPI 2: v = e1[idx] - e2[idx] * coef * (acc + ev0[row]*ev1[col])
// EPI 3: v = acc + e1[idx]
// EPI 4: v = acc + e0[col]
// TW 0: write C only.  TW 1: write C and CT (=C^T).  TW 2: write CT only.
// ---------------------------------------------------------------------------
template <int EPI, bool RND, int TW>
__global__ void __launch_bounds__(128, 2)
ntgemm3(const float* __restrict__ A, const float* __restrict__ B,
        float* __restrict__ C, float* __restrict__ CT, int M, int N, int K,
        const float* __restrict__ e0, const float* __restrict__ e1,
        const float* __restrict__ e2, const float* __restrict__ ev0,
        const float* __restrict__ ev1, float coef)
{
    constexpr int BK   = 32;
    constexpr int TILE = 128 * BK * 4;
    constexpr int SS   = 2 * TILE;

    extern __shared__ __align__(128) char smraw[];
    const uint32_t sb = (uint32_t)__cvta_generic_to_shared(smraw);

    const int tid  = threadIdx.x;
    const int lane = tid & 31;
    const int wid  = tid >> 5;
    const int wm   = (wid & 1) * 64;
    const int wn   = (wid >> 1) * 64;
    const int m0   = blockIdx.y * 128;
    const int n0   = blockIdx.x * 128;

    const int lr = tid >> 3;
    const int lc = tid & 7;
    const uint32_t lOff = (uint32_t)(lr * 128 + ((lc ^ (lr & 7)) << 4));
    const float* aG = A + (size_t)(m0 + lr) * K + lc * 4;
    const float* bG = B + (size_t)(n0 + lr) * K + lc * 4;

    auto loadTile = [&](int t) {
        const uint32_t base = sb + (uint32_t)((t % 3) * SS);
        const float* a = aG + (size_t)t * BK;
        const float* b = bG + (size_t)t * BK;
#pragma unroll
        for (int i = 0; i < 8; ++i)
            cp16(base + lOff + 2048u * i, a + (size_t)(16 * i) * K);
#pragma unroll
        for (int i = 0; i < 8; ++i)
            cp16(base + TILE + lOff + 2048u * i, b + (size_t)(16 * i) * K);
        asm volatile("cp.async.commit_group;" ::: "memory");
    };

    const int rr  = lane & 7;
    const int loA = (lane >> 3) & 1;
    const int hiA = (lane >> 4) & 1;
    const int loB = (lane >> 4) & 1;
    const int hiB = (lane >> 3) & 1;
    const uint32_t swz = (uint32_t)rr << 4;

    uint32_t aRow[4], bRow[4];
#pragma unroll
    for (int mf = 0; mf < 4; ++mf)
        aRow[mf] = (uint32_t)((wm + mf * 16 + loA * 8 + rr) * 128);
#pragma unroll
    for (int nfp = 0; nfp < 4; ++nfp)
        bRow[nfp] = (uint32_t)((wn + nfp * 16 + loB * 8 + rr) * 128);

    float acc[4][8][4];
#pragma unroll
    for (int i = 0; i < 4; ++i)
#pragma unroll
        for (int j = 0; j < 8; ++j)
#pragma unroll
            for (int k = 0; k < 4; ++k) acc[i][j][k] = 0.0f;

    const int nt = K / BK;
    loadTile(0);
    loadTile(1);

    for (int t = 0; t < nt; ++t) {
        if (t + 1 < nt) asm volatile("cp.async.wait_group 1;" ::: "memory");
        else            asm volatile("cp.async.wait_group 0;" ::: "memory");
        __syncthreads();
        if (t + 2 < nt) loadTile(t + 2);

        const uint32_t stA = sb + (uint32_t)((t % 3) * SS);
        const uint32_t stB = stA + TILE;

#pragma unroll
        for (int kk = 0; kk < 4; ++kk) {
            const uint32_t ak = (((uint32_t)(2 * kk + hiA)) << 4) ^ swz;
            const uint32_t bk = (((uint32_t)(2 * kk + hiB)) << 4) ^ swz;
            uint32_t af[4][4];
#pragma unroll
            for (int mf = 0; mf < 4; ++mf)
                ldsm4(af[mf][0], af[mf][1], af[mf][2], af[mf][3], stA + aRow[mf] + ak);
            uint32_t bf[4][4];
#pragma unroll
            for (int nfp = 0; nfp < 4; ++nfp)
                ldsm4(bf[nfp][0], bf[nfp][1], bf[nfp][2], bf[nfp][3], stB + bRow[nfp] + bk);
#pragma unroll
            for (int mf = 0; mf < 4; ++mf)
#pragma unroll
                for (int nf = 0; nf < 8; ++nf)
                    mma_tf32(acc[mf][nf], af[mf],
                             bf[nf >> 1][(nf & 1) * 2], bf[nf >> 1][(nf & 1) * 2 + 1]);
        }
    }

    // ---- epilogue ----
    const int g   = lane >> 2;
    const int tig = lane & 3;
    float* esm = reinterpret_cast<float*>(smraw);
    if (TW) __syncthreads();

#pragma unroll
    for (int mf = 0; mf < 4; ++mf) {
#pragma unroll
        for (int nf = 0; nf < 8; ++nf) {
#pragma unroll
            for (int h = 0; h < 2; ++h) {
                const int rl = wm + mf * 16 + g + h * 8;
                const int cl = wn + nf * 8 + 2 * tig;
                const int r = m0 + rl;
                const int c = n0 + cl;
                const size_t idx = (size_t)r * N + c;
                float v0 = acc[mf][nf][h * 2 + 0];
                float v1 = acc[mf][nf][h * 2 + 1];
                if (EPI == 1) {
                    const float2 a1 = *reinterpret_cast<const float2*>(e1 + idx);
                    const float2 a2 = *reinterpret_cast<const float2*>(e2 + idx);
                    v0 += a1.x - a2.x;
                    v1 += a1.y - a2.y;
                } else if (EPI == 2) {
                    const float2 w  = *reinterpret_cast<const float2*>(e1 + idx);
                    const float2 lr = *reinterpret_cast<const float2*>(e2 + idx);
                    const float bi  = ev0[r];
                    const float g0  = coef * (v0 + bi * ev1[c]);
                    const float g1  = coef * (v1 + bi * ev1[c + 1]);
                    v0 = w.x - lr.x * g0;
                    v1 = w.y - lr.y * g1;
                } else if (EPI == 3) {
                    const float2 a1 = *reinterpret_cast<const float2*>(e1 + idx);
                    v0 += a1.x;
                    v1 += a1.y;
                } else if (EPI == 4) {
                    v0 += e0[c];
                    v1 += e0[c + 1];
                }
                if (RND) { v0 = rnd_tf32(v0); v1 = rnd_tf32(v1); }
                if (TW != 2) {
                    float2 out; out.x = v0; out.y = v1;
                    *reinterpret_cast<float2*>(C + idx) = out;
                }
                if (TW) {
                    esm[(cl + 0) * 132 + rl] = v0;
                    esm[(cl + 1) * 132 + rl] = v1;
                }
            }
        }
    }

    if (TW) {
        __syncthreads();
#pragma unroll
        for (int i = 0; i < 32; ++i) {
            const int chunk = tid + (i << 7);
            const int row  = chunk >> 5;
            const int col4 = (chunk & 31) << 2;
            const float4 v = *reinterpret_cast<const float4*>(esm + row * 132 + col4);
            *reinterpret_cast<float4*>(CT + (size_t)(n0 + row) * M + m0 + col4) = v;
        }
    }
}

// ---------------------------------------------------------------------------
// Symmetric Gram GEMM, 4-warp/64x64, 3-stage, occ 2. Lower-triangle tiles +
// mirror of off-diagonal blocks via smem transpose stage.
// ---------------------------------------------------------------------------
__global__ void __launch_bounds__(128, 2)
symgemm4(const float* __restrict__ A, float* __restrict__ C, int N, int K)
{
    constexpr int BK   = 32;
    constexpr int TILE = 128 * BK * 4;
    constexpr int SS   = 2 * TILE;

    extern __shared__ __align__(128) char smraw[];
    const uint32_t sb = (uint32_t)__cvta_generic_to_shared(smraw);

    const int tid  = threadIdx.x;
    const int lane = tid & 31;
    const int wid  = tid >> 5;
    const int wm   = (wid & 1) * 64;
    const int wn   = (wid >> 1) * 64;

    const int i = blockIdx.x;
    int e = (int)((sqrtf(8.0f * (float)i + 1.0f) - 1.0f) * 0.5f);
    while ((e + 1) * (e + 2) / 2 <= i) ++e;
    while (e * (e + 1) / 2 > i) --e;
    const int by = e;
    const int bx = i - e * (e + 1) / 2;
    const int m0 = by * 128;
    const int n0 = bx * 128;

    const int lr = tid >> 3;
    const int lc = tid & 7;
    const uint32_t lOff = (uint32_t)(lr * 128 + ((lc ^ (lr & 7)) << 4));
    const float* aG = A + (size_t)(m0 + lr) * K + lc * 4;
    const float* bG = A + (size_t)(n0 + lr) * K + lc * 4;

    auto loadTile = [&](int t) {
        const uint32_t base = sb + (uint32_t)((t % 3) * SS);
        const float* a = aG + (size_t)t * BK;
        const float* b = bG + (size_t)t * BK;
#pragma unroll
        for (int ii = 0; ii < 8; ++ii)
            cp16(base + lOff + 2048u * ii, a + (size_t)(16 * ii) * K);
#pragma unroll
        for (int ii = 0; ii < 8; ++ii)
            cp16(base + TILE + lOff + 2048u * ii, b + (size_t)(16 * ii) * K);
        asm volatile("cp.async.commit_group;" ::: "memory");
    };

    const int rr  = lane & 7;
    const int loA = (lane >> 3) & 1;
    const int hiA = (lane >> 4) & 1;
    const int loB = (lane >> 4) & 1;
    const int hiB = (lane >> 3) & 1;
    const uint32_t swz = (uint32_t)rr << 4;

    uint32_t aRow[4], bRow[4];
#pragma unroll
    for (int mf = 0; mf < 4; ++mf)
        aRow[mf] = (uint32_t)((wm + mf * 16 + loA * 8 + rr) * 128);
#pragma unroll
    for (int nfp = 0; nfp < 4; ++nfp)
        bRow[nfp] = (uint32_t)((wn + nfp * 16 + loB * 8 + rr) * 128);

    float acc[4][8][4];
#pragma unroll
    for (int a = 0; a < 4; ++a)
#pragma unroll
        for (int b = 0; b < 8; ++b)
#pragma unroll
            for (int k = 0; k < 4; ++k) acc[a][b][k] = 0.0f;

    const int nt = K / BK;
    loadTile(0);
    loadTile(1);

    for (int t = 0; t < nt; ++t) {
        if (t + 1 < nt) asm volatile("cp.async.wait_group 1;" ::: "memory");
        else            asm volatile("cp.async.wait_group 0;" ::: "memory");
        __syncthreads();
        if (t + 2 < nt) loadTile(t + 2);

        const uint32_t stA = sb + (uint32_t)((t % 3) * SS);
        const uint32_t stB = stA + TILE;

#pragma unroll
        for (int kk = 0; kk < 4; ++kk) {
            const uint32_t ak = (((uint32_t)(2 * kk + hiA)) << 4) ^ swz;
            const uint32_t bk = (((uint32_t)(2 * kk + hiB)) << 4) ^ swz;
            uint32_t af[4][4];
#pragma unroll
            for (int mf = 0; mf < 4; ++mf)
                ldsm4(af[mf][0], af[mf][1], af[mf][2], af[mf][3], stA + aRow[mf] + ak);
            uint32_t bf[4][4];
#pragma unroll
            for (int nfp = 0; nfp < 4; ++nfp)
                ldsm4(bf[nfp][0], bf[nfp][1], bf[nfp][2], bf[nfp][3], stB + bRow[nfp] + bk);
#pragma unroll
            for (int mf = 0; mf < 4; ++mf)
#pragma unroll
                for (int nf = 0; nf < 8; ++nf)
                    mma_tf32(acc[mf][nf], af[mf],
                             bf[nf >> 1][(nf & 1) * 2], bf[nf >> 1][(nf & 1) * 2 + 1]);
        }
    }

    const int g   = lane >> 2;
    const int tig = lane & 3;
    float* esm = reinterpret_cast<float*>(smraw);
    const bool mirror = (bx != by);
    if (mirror) __syncthreads();

#pragma unroll
    for (int mf = 0; mf < 4; ++mf) {
#pragma unroll
        for (int nf = 0; nf < 8; ++nf) {
#pragma unroll
            for (int h = 0; h < 2; ++h) {
                const int rl = wm + mf * 16 + g + h * 8;
                const int cl = wn + nf * 8 + 2 * tig;
                float v0 = rnd_tf32(acc[mf][nf][h * 2 + 0]);
                float v1 = rnd_tf32(acc[mf][nf][h * 2 + 1]);
                float2 out; out.x = v0; out.y = v1;
                *reinterpret_cast<float2*>(C + (size_t)(m0 + rl) * N + n0 + cl) = out;
                if (mirror) {
                    esm[(cl + 0) * 132 + rl] = v0;
                    esm[(cl + 1) * 132 + rl] = v1;
                }
            }
        }
    }

    if (mirror) {
        __syncthreads();
#pragma unroll
        for (int ii = 0; ii < 32; ++ii) {
            const int chunk = tid + (ii << 7);
            const int row  = chunk >> 5;
            const int col4 = (chunk & 31) << 2;
            const float4 v = *reinterpret_cast<const float4*>(esm + row * 132 + col4);
            *reinterpret_cast<float4*>(C + (size_t)(n0 + row) * N + m0 + col4) = v;
        }
    }
}

// ---------------- small kernels ----------------------------------------------
__global__ void round_kernel(const float* __restrict__ in, float* __restrict__ out, int n4)
{
    int i = blockIdx.x * blockDim.x + threadIdx.x;
    if (i < n4) {
        float4 v = reinterpret_cast<const float4*>(in)[i];
        v.x = rnd_tf32(v.x); v.y = rnd_tf32(v.y);
        v.z = rnd_tf32(v.z); v.w = rnd_tf32(v.w);
        reinterpret_cast<float4*>(out)[i] = v;
    }
}

__global__ void round_and_T(const float* __restrict__ in, float* __restrict__ outR,
                            float* __restrict__ outT, int R, int C)
{
    __shared__ float tile[32][33];
    const int bx = blockIdx.x * 32, by = blockIdx.y * 32;
    const int x = threadIdx.x, y = threadIdx.y;
#pragma unroll
    for (int j = 0; j < 32; j += 8) {
        const float v = rnd_tf32(in[(size_t)(by + y + j) * C + bx + x]);
        tile[y + j][x] = v;
        outR[(size_t)(by + y + j) * C + bx + x] = v;
    }
    __syncthreads();
#pragma unroll
    for (int j = 0; j < 32; j += 8)
        outT[(size_t)(bx + y + j) * R + by + x] = tile[x][y + j];
}

__global__ void colsum_kernel(const float* __restrict__ in, float* __restrict__ part)
{
    int col = blockIdx.x * blockDim.x + threadIdx.x;
    int chunk = blockIdx.y;
    const float* p = in + (size_t)chunk * 128 * D_DIM + col;
    float s0 = 0.f, s1 = 0.f, s2 = 0.f, s3 = 0.f;
#pragma unroll
    for (int r = 0; r < 128; r += 4) {
        s0 += p[(size_t)(r + 0) * D_DIM];
        s1 += p[(size_t)(r + 1) * D_DIM];
        s2 += p[(size_t)(r + 2) * D_DIM];
        s3 += p[(size_t)(r + 3) * D_DIM];
    }
    part[chunk * D_DIM + col] = (s0 + s1) + (s2 + s3);
}

__global__ void creduce_kernel(const float* __restrict__ part, float* __restrict__ c)
{
    int j = blockIdx.x * blockDim.x + threadIdx.x;
    float s = 0.f;
#pragma unroll
    for (int ch = 0; ch < 32; ++ch) s += part[ch * D_DIM + j];
    c[j] = s;
}

__global__ void vecmat_kernel(const float* __restrict__ vec, const float* __restrict__ Mat,
                              float* __restrict__ outv)
{
    int j = blockIdx.x * blockDim.x + threadIdx.x;
    float s0 = 0.f, s1 = 0.f, s2 = 0.f, s3 = 0.f;
#pragma unroll 4
    for (int k = 0; k < D_DIM; k += 4) {
        s0 += vec[k + 0] * Mat[(size_t)(k + 0) * D_DIM + j];
        s1 += vec[k + 1] * Mat[(size_t)(k + 1) * D_DIM + j];
        s2 += vec[k + 2] * Mat[(size_t)(k + 2) * D_DIM + j];
        s3 += vec[k + 3] * Mat[(size_t)(k + 3) * D_DIM + j];
    }
    outv[j] = (s0 + s1) + (s2 + s3);
}

__global__ void bn_kernel(const float* __restrict__ Mm, const float* __restrict__ c,
                          const float* __restrict__ b, const float* __restrict__ lrb,
                          float* __restrict__ bn, float coef)
{
    int j = blockIdx.x * blockDim.x + threadIdx.x;
    float s0 = 0.f, s1 = 0.f, s2 = 0.f, s3 = 0.f;
#pragma unroll 4
    for (int k = 0; k < D_DIM; k += 4) {
        s0 += c[k + 0] * Mm[(size_t)(k + 0) * D_DIM + j];
        s1 += c[k + 1] * Mm[(size_t)(k + 1) * D_DIM + j];
        s2 += c[k + 2] * Mm[(size_t)(k + 2) * D_DIM + j];
        s3 += c[k + 3] * Mm[(size_t)(k + 3) * D_DIM + j];
    }
    float s = (s0 + s1) + (s2 + s3);
    bn[j] = b[j] - lrb[j] * coef * (s + (float)B_TOK * b[j]);
}

// ---------------- host --------------------------------------------------------
extern "C" void kernel_launch(void* const* d_in, const int* in_sizes, int n_in,
                              void* d_out, int out_size)
{
    const float* src  = (const float*)d_in[0];
    const float* th_k = (const float*)d_in[1];
    const float* th_q = (const float*)d_in[2];
    const float* th_v = (const float*)d_in[3];
    const float* W    = (const float*)d_in[4];
    const float* b    = (const float*)d_in[5];
    const float* lr_w = (const float*)d_in[6];
    const float* lr_b = (const float*)d_in[7];
    float* out = (float*)d_out;

    float *srcR, *srcT, *thkR, *thqR, *WR, *thkT, *S, *Mm, *MT, *T1T, *Wn, *PT;
    float *part, *cvec, *vvec, *bn;
    cudaGetSymbolAddress((void**)&srcR, g_srcR);
    cudaGetSymbolAddress((void**)&srcT, g_srcT);
    cudaGetSymbolAddress((void**)&thkR, g_thkR);
    cudaGetSymbolAddress((void**)&thqR, g_thqR);
    cudaGetSymbolAddress((void**)&WR,   g_WR);
    cudaGetSymbolAddress((void**)&thkT, g_thkT);
    cudaGetSymbolAddress((void**)&S,    g_S);
    cudaGetSymbolAddress((void**)&Mm,   g_M);
    cudaGetSymbolAddress((void**)&MT,   g_MT);
    cudaGetSymbolAddress((void**)&T1T,  g_T1T);
    cudaGetSymbolAddress((void**)&Wn,   g_Wn);
    cudaGetSymbolAddress((void**)&PT,   g_PT);
    cudaGetSymbolAddress((void**)&part, g_part);
    cudaGetSymbolAddress((void**)&cvec, g_c);
    cudaGetSymbolAddress((void**)&vvec, g_v);
    cudaGetSymbolAddress((void**)&bn,   g_bn);

    // Created once on the first (non-capture) correctness call; reused in capture.
    static cudaStream_t s2 = nullptr;
    static cudaEvent_t evFork = nullptr, evJoin = nullptr;
    if (s2 == nullptr) {
        cudaStreamCreateWithFlags(&s2, cudaStreamNonBlocking);
        cudaEventCreateWithFlags(&evFork, cudaEventDisableTiming);
        cudaEventCreateWithFlags(&evJoin, cudaEventDisableTiming);
    }

    const float coef = 2.0f / ((float)B_TOK * (float)D_DIM);
    const int SMEM3 = 3 * 2 * 128 * 32 * 4;   // 98304

    cudaFuncSetAttribute(ntgemm3<1, true,  1>, cudaFuncAttributeMaxDynamicSharedMemorySize, SMEM3);
    cudaFuncSetAttribute(ntgemm3<0, true,  2>, cudaFuncAttributeMaxDynamicSharedMemorySize, SMEM3);
    cudaFuncSetAttribute(ntgemm3<2, true,  0>, cudaFuncAttributeMaxDynamicSharedMemorySize, SMEM3);
    cudaFuncSetAttribute(ntgemm3<3, true,  2>, cudaFuncAttributeMaxDynamicSharedMemorySize, SMEM3);
    cudaFuncSetAttribute(ntgemm3<4, false, 0>, cudaFuncAttributeMaxDynamicSharedMemorySize, SMEM3);
    cudaFuncSetAttribute(symgemm4,             cudaFuncAttributeMaxDynamicSharedMemorySize, SMEM3);

    dim3 tb(32, 8);
    dim3 gridD(D_DIM / 128, D_DIM / 128);   // 256 CTAs
    dim3 gridZ(D_DIM / 128, B_TOK / 128);   // 512 CTAs
    const int nSymTiles = (D_DIM / 128) * (D_DIM / 128 + 1) / 2;   // 136

    // prep on main stream
    round_and_T<<<dim3(D_DIM / 32, B_TOK / 32), tb>>>(src, srcR, srcT, B_TOK, D_DIM);
    round_and_T<<<dim3(D_DIM / 32, D_DIM / 32), tb>>>(th_k, thkR, thkT, D_DIM, D_DIM);

    // ---- fork: independent branch (W round, M-GEMM, thq round) on s2 ----
    cudaEventRecord(evFork, 0);
    cudaStreamWaitEvent(s2, evFork, 0);
    round_kernel<<<(D_DIM * D_DIM / 4 + 255) / 256, 256, 0, s2>>>(W, WR, D_DIM * D_DIM / 4);
    ntgemm3<1, true, 1><<<gridD, 128, SMEM3, s2>>>(thkR, WR, Mm, MT, D_DIM, D_DIM, D_DIM,
                                                   nullptr, th_k, th_v, nullptr, nullptr, 0.f);
    round_kernel<<<(D_DIM * D_DIM / 4 + 255) / 256, 256, 0, s2>>>(th_q, thqR, D_DIM * D_DIM / 4);
    cudaEventRecord(evJoin, s2);

    // ---- main chain ----
    colsum_kernel<<<dim3(D_DIM / 256, 32), 256>>>(src, part);
    symgemm4<<<nSymTiles, 128, SMEM3>>>(srcT, S, D_DIM, B_TOK);
    creduce_kernel<<<D_DIM / 256, 256>>>(part, cvec);
    vecmat_kernel<<<D_DIM / 128, 128>>>(cvec, th_k, vvec);

    // T1T = (S @ theta_k)^T   (rounded)
    ntgemm3<0, true, 2><<<gridD, 128, SMEM3>>>(S, thkT, nullptr, T1T, D_DIM, D_DIM, D_DIM,
                                               nullptr, nullptr, nullptr, nullptr, nullptr, 0.f);

    // join: Wn needs MT; bn needs Mm; P needs thqR
    cudaStreamWaitEvent(0, evJoin, 0);

    bn_kernel<<<D_DIM / 128, 128>>>(Mm, cvec, b, lr_b, bn, coef);

    // Wn = W - lr_w * coef * (M^T @ T1 + b (x) v)
    ntgemm3<2, true, 0><<<gridD, 128, SMEM3>>>(MT, T1T, Wn, nullptr, D_DIM, D_DIM, D_DIM,
                                               nullptr, W, lr_w, b, vvec, coef);

    // PT = (theta_q @ Wn^T + theta_q)^T   (rounded)
    ntgemm3<3, true, 2><<<gridD, 128, SMEM3>>>(thqR, Wn, nullptr, PT, D_DIM, D_DIM, D_DIM,
                                               nullptr, th_q, nullptr, nullptr, nullptr, 0.f);

    // z = src @ P + bn
    ntgemm3<4, false, 0><<<gridZ, 128, SMEM3>>>(srcR, PT, out, nullptr, B_TOK, D_DIM, D_DIM,
                                                bn, nullptr, nullptr, nullptr, nullptr, 0.f);
}

// round 11
// speedup vs baseline: 1.2880x; 1.2249x over previous
#include <cuda_runtime.h>
#include <cuda_fp16.h>
#include <cstdint>
#include <math.h>

#define D_DIM 2048
#define B_TOK 4096

// ---------------- scratch (device globals; no allocation allowed) ----------
__device__ float  g_srcR[(size_t)B_TOK * D_DIM];   // tf32-rounded src (z A-operand)
__device__ __half g_srcTh[(size_t)B_TOK * D_DIM];  // half src^T (S operand)
__device__ __half g_thkRh[(size_t)D_DIM * D_DIM];  // half theta_k (M A-operand)
__device__ __half g_thkTh[(size_t)D_DIM * D_DIM];  // half theta_k^T (T1 B-operand)
__device__ __half g_WRh [(size_t)D_DIM * D_DIM];   // half W (M B-operand)
__device__ float  g_thqR[(size_t)D_DIM * D_DIM];   // tf32 theta_q (P A-operand)
__device__ __half g_Sh  [(size_t)D_DIM * D_DIM];   // half S
__device__ float  g_M   [(size_t)D_DIM * D_DIM];   // fp32 M (for bn)
__device__ __half g_MTh [(size_t)D_DIM * D_DIM];   // half M^T (gW A)
__device__ __half g_T1Th[(size_t)D_DIM * D_DIM];   // half T1^T (gW B)
__device__ float  g_Wn  [(size_t)D_DIM * D_DIM];   // tf32 Wn
__device__ float  g_PT  [(size_t)D_DIM * D_DIM];   // tf32 P^T
__device__ float  g_part[32 * D_DIM];
__device__ float  g_c   [D_DIM];
__device__ float  g_v   [D_DIM];
__device__ float  g_bn  [D_DIM];

// ---------------- PTX helpers ----------------------------------------------
__device__ __forceinline__ float rnd_tf32(float x) {
    uint32_t r;
    asm("cvt.rna.tf32.f32 %0, %1;" : "=r"(r) : "f"(x));
    return __uint_as_float(r);
}

__device__ __forceinline__ void cp16(uint32_t dst, const void* src) {
    asm volatile("cp.async.cg.shared.global [%0], [%1], 16;" :: "r"(dst), "l"(src));
}

__device__ __forceinline__ void ldsm4(uint32_t& r0, uint32_t& r1, uint32_t& r2, uint32_t& r3,
                                      uint32_t addr) {
    asm volatile("ldmatrix.sync.aligned.m8n8.x4.shared.b16 {%0,%1,%2,%3}, [%4];"
                 : "=r"(r0), "=r"(r1), "=r"(r2), "=r"(r3) : "r"(addr));
}

__device__ __forceinline__ void mma_tf32(float c[4], const uint32_t a[4],
                                         uint32_t b0, uint32_t b1) {
    asm volatile(
        "mma.sync.aligned.m16n8k8.row.col.f32.tf32.tf32.f32 "
        "{%0,%1,%2,%3}, {%4,%5,%6,%7}, {%8,%9}, {%0,%1,%2,%3};"
        : "+f"(c[0]), "+f"(c[1]), "+f"(c[2]), "+f"(c[3])
        : "r"(a[0]), "r"(a[1]), "r"(a[2]), "r"(a[3]), "r"(b0), "r"(b1));
}

__device__ __forceinline__ void mma_f16(float c[4], const uint32_t a[4],
                                        uint32_t b0, uint32_t b1) {
    asm volatile(
        "mma.sync.aligned.m16n8k16.row.col.f32.f16.f16.f32 "
        "{%0,%1,%2,%3}, {%4,%5,%6,%7}, {%8,%9}, {%0,%1,%2,%3};"
        : "+f"(c[0]), "+f"(c[1]), "+f"(c[2]), "+f"(c[3])
        : "r"(a[0]), "r"(a[1]), "r"(a[2]), "r"(a[3]), "r"(b0), "r"(b1));
}

// ---------------------------------------------------------------------------
// tf32 4-warp NT GEMM (proven): CTA 128x128, 4 warps 64x64, BK=32, 3-stage.
// EPI 3: v = acc + e1[idx]       EPI 4: v = acc + e0[col]
// TW 0: write C.  TW 2: write CT only (half-precision staging in fp32 smem).
// ---------------------------------------------------------------------------
template <int EPI, bool RND, int TW>
__global__ void __launch_bounds__(128, 2)
ntgemm3(const float* __restrict__ A, const float* __restrict__ B,
        float* __restrict__ C, float* __restrict__ CT, int M, int N, int K,
        const float* __restrict__ e0, const float* __restrict__ e1)
{
    constexpr int BK   = 32;
    constexpr int TILE = 128 * BK * 4;
    constexpr int SS   = 2 * TILE;

    extern __shared__ __align__(128) char smraw[];
    const uint32_t sb = (uint32_t)__cvta_generic_to_shared(smraw);

    const int tid  = threadIdx.x;
    const int lane = tid & 31;
    const int wid  = tid >> 5;
    const int wm   = (wid & 1) * 64;
    const int wn   = (wid >> 1) * 64;
    const int m0   = blockIdx.y * 128;
    const int n0   = blockIdx.x * 128;

    const int lr = tid >> 3;
    const int lc = tid & 7;
    const uint32_t lOff = (uint32_t)(lr * 128 + ((lc ^ (lr & 7)) << 4));
    const float* aG = A + (size_t)(m0 + lr) * K + lc * 4;
    const float* bG = B + (size_t)(n0 + lr) * K + lc * 4;

    auto loadTile = [&](int t) {
        const uint32_t base = sb + (uint32_t)((t % 3) * SS);
        const float* a = aG + (size_t)t * BK;
        const float* b = bG + (size_t)t * BK;
#pragma unroll
        for (int i = 0; i < 8; ++i)
            cp16(base + lOff + 2048u * i, a + (size_t)(16 * i) * K);
#pragma unroll
        for (int i = 0; i < 8; ++i)
            cp16(base + TILE + lOff + 2048u * i, b + (size_t)(16 * i) * K);
        asm volatile("cp.async.commit_group;" ::: "memory");
    };

    const int rr  = lane & 7;
    const int loA = (lane >> 3) & 1;
    const int hiA = (lane >> 4) & 1;
    const int loB = (lane >> 4) & 1;
    const int hiB = (lane >> 3) & 1;
    const uint32_t swz = (uint32_t)rr << 4;

    uint32_t aRow[4], bRow[4];
#pragma unroll
    for (int mf = 0; mf < 4; ++mf)
        aRow[mf] = (uint32_t)((wm + mf * 16 + loA * 8 + rr) * 128);
#pragma unroll
    for (int nfp = 0; nfp < 4; ++nfp)
        bRow[nfp] = (uint32_t)((wn + nfp * 16 + loB * 8 + rr) * 128);

    float acc[4][8][4];
#pragma unroll
    for (int i = 0; i < 4; ++i)
#pragma unroll
        for (int j = 0; j < 8; ++j)
#pragma unroll
            for (int k = 0; k < 4; ++k) acc[i][j][k] = 0.0f;

    const int nt = K / BK;
    loadTile(0);
    loadTile(1);

    for (int t = 0; t < nt; ++t) {
        if (t + 1 < nt) asm volatile("cp.async.wait_group 1;" ::: "memory");
        else            asm volatile("cp.async.wait_group 0;" ::: "memory");
        __syncthreads();
        if (t + 2 < nt) loadTile(t + 2);

        const uint32_t stA = sb + (uint32_t)((t % 3) * SS);
        const uint32_t stB = stA + TILE;

#pragma unroll
        for (int kk = 0; kk < 4; ++kk) {
            const uint32_t ak = (((uint32_t)(2 * kk + hiA)) << 4) ^ swz;
            const uint32_t bk = (((uint32_t)(2 * kk + hiB)) << 4) ^ swz;
            uint32_t af[4][4];
#pragma unroll
            for (int mf = 0; mf < 4; ++mf)
                ldsm4(af[mf][0], af[mf][1], af[mf][2], af[mf][3], stA + aRow[mf] + ak);
            uint32_t bf[4][4];
#pragma unroll
            for (int nfp = 0; nfp < 4; ++nfp)
                ldsm4(bf[nfp][0], bf[nfp][1], bf[nfp][2], bf[nfp][3], stB + bRow[nfp] + bk);
#pragma unroll
            for (int mf = 0; mf < 4; ++mf)
#pragma unroll
                for (int nf = 0; nf < 8; ++nf)
                    mma_tf32(acc[mf][nf], af[mf],
                             bf[nf >> 1][(nf & 1) * 2], bf[nf >> 1][(nf & 1) * 2 + 1]);
        }
    }

    const int g   = lane >> 2;
    const int tig = lane & 3;
    float* esm = reinterpret_cast<float*>(smraw);
    if (TW) __syncthreads();

#pragma unroll
    for (int mf = 0; mf < 4; ++mf) {
#pragma unroll
        for (int nf = 0; nf < 8; ++nf) {
#pragma unroll
            for (int h = 0; h < 2; ++h) {
                const int rl = wm + mf * 16 + g + h * 8;
                const int cl = wn + nf * 8 + 2 * tig;
                const size_t idx = (size_t)(m0 + rl) * N + n0 + cl;
                float v0 = acc[mf][nf][h * 2 + 0];
                float v1 = acc[mf][nf][h * 2 + 1];
                if (EPI == 3) {
                    const float2 a1 = *reinterpret_cast<const float2*>(e1 + idx);
                    v0 += a1.x; v1 += a1.y;
                } else if (EPI == 4) {
                    v0 += e0[n0 + cl]; v1 += e0[n0 + cl + 1];
                }
                if (RND) { v0 = rnd_tf32(v0); v1 = rnd_tf32(v1); }
                if (TW != 2) {
                    float2 out; out.x = v0; out.y = v1;
                    *reinterpret_cast<float2*>(C + idx) = out;
                }
                if (TW) {
                    esm[(cl + 0) * 132 + rl] = v0;
                    esm[(cl + 1) * 132 + rl] = v1;
                }
            }
        }
    }

    if (TW) {
        __syncthreads();
#pragma unroll
        for (int i = 0; i < 32; ++i) {
            const int chunk = tid + (i << 7);
            const int row  = chunk >> 5;
            const int col4 = (chunk & 31) << 2;
            const float4 v = *reinterpret_cast<const float4*>(esm + row * 132 + col4);
            *reinterpret_cast<float4*>(CT + (size_t)(n0 + row) * M + m0 + col4) = v;
        }
    }
}

// ---------------------------------------------------------------------------
// fp16 4-warp NT GEMM: C[M,N] = A[M,K]*B[N,K]^T, fp32 accumulate.
// CTA 128x128, 4 warps 64x64, BK=64 halves (128B rows — identical smem layout,
// swizzle, and ldsm addressing as tf32; each kk covers K=16). 3-stage, occ 2.
// EPI 0: v = acc
// EPI 1: v = acc + e1[idx] - e2[idx]                      (fp32 side inputs)
// EPI 2: v = e1[idx] - e2[idx]*coef*(acc + ev0[r]*ev1[c]) (fp32 side inputs)
// MODE 0: C fp32 (RND->tf32).  MODE 1: CTh half only.  MODE 2: C fp32 + CTh.
// ---------------------------------------------------------------------------
template <int EPI, int MODE>
__global__ void __launch_bounds__(128, 2)
hgemm(const __half* __restrict__ A, const __half* __restrict__ B,
      float* __restrict__ C, __half* __restrict__ CTh, int M, int N, int K,
      const float* __restrict__ e1, const float* __restrict__ e2,
      const float* __restrict__ ev0, const float* __restrict__ ev1, float coef)
{
    constexpr int BK   = 64;             // halves
    constexpr int TILE = 128 * 128;      // bytes (128 rows x 128B)
    constexpr int SS   = 2 * TILE;

    extern __shared__ __align__(128) char smraw[];
    const uint32_t sb = (uint32_t)__cvta_generic_to_shared(smraw);

    const int tid  = threadIdx.x;
    const int lane = tid & 31;
    const int wid  = tid >> 5;
    const int wm   = (wid & 1) * 64;
    const int wn   = (wid >> 1) * 64;
    const int m0   = blockIdx.y * 128;
    const int n0   = blockIdx.x * 128;

    const int lr = tid >> 3;
    const int lc = tid & 7;
    const uint32_t lOff = (uint32_t)(lr * 128 + ((lc ^ (lr & 7)) << 4));
    const __half* aG = A + (size_t)(m0 + lr) * K + lc * 8;
    const __half* bG = B + (size_t)(n0 + lr) * K + lc * 8;

    auto loadTile = [&](int t) {
        const uint32_t base = sb + (uint32_t)((t % 3) * SS);
        const __half* a = aG + (size_t)t * BK;
        const __half* b = bG + (size_t)t * BK;
#pragma unroll
        for (int i = 0; i < 8; ++i)
            cp16(base + lOff + 2048u * i, a + (size_t)(16 * i) * K);
#pragma unroll
        for (int i = 0; i < 8; ++i)
            cp16(base + TILE + lOff + 2048u * i, b + (size_t)(16 * i) * K);
        asm volatile("cp.async.commit_group;" ::: "memory");
    };

    const int rr  = lane & 7;
    const int loA = (lane >> 3) & 1;
    const int hiA = (lane >> 4) & 1;
    const int loB = (lane >> 4) & 1;
    const int hiB = (lane >> 3) & 1;
    const uint32_t swz = (uint32_t)rr << 4;

    uint32_t aRow[4], bRow[4];
#pragma unroll
    for (int mf = 0; mf < 4; ++mf)
        aRow[mf] = (uint32_t)((wm + mf * 16 + loA * 8 + rr) * 128);
#pragma unroll
    for (int nfp = 0; nfp < 4; ++nfp)
        bRow[nfp] = (uint32_t)((wn + nfp * 16 + loB * 8 + rr) * 128);

    float acc[4][8][4];
#pragma unroll
    for (int i = 0; i < 4; ++i)
#pragma unroll
        for (int j = 0; j < 8; ++j)
#pragma unroll
            for (int k = 0; k < 4; ++k) acc[i][j][k] = 0.0f;

    const int nt = K / BK;
    loadTile(0);
    loadTile(1);

    for (int t = 0; t < nt; ++t) {
        if (t + 1 < nt) asm volatile("cp.async.wait_group 1;" ::: "memory");
        else            asm volatile("cp.async.wait_group 0;" ::: "memory");
        __syncthreads();
        if (t + 2 < nt) loadTile(t + 2);

        const uint32_t stA = sb + (uint32_t)((t % 3) * SS);
        const uint32_t stB = stA + TILE;

#pragma unroll
        for (int kk = 0; kk < 4; ++kk) {    // each kk = K16
            const uint32_t ak = (((uint32_t)(2 * kk + hiA)) << 4) ^ swz;
            const uint32_t bk = (((uint32_t)(2 * kk + hiB)) << 4) ^ swz;
            uint32_t af[4][4];
#pragma unroll
            for (int mf = 0; mf < 4; ++mf)
                ldsm4(af[mf][0], af[mf][1], af[mf][2], af[mf][3], stA + aRow[mf] + ak);
            uint32_t bf[4][4];
#pragma unroll
            for (int nfp = 0; nfp < 4; ++nfp)
                ldsm4(bf[nfp][0], bf[nfp][1], bf[nfp][2], bf[nfp][3], stB + bRow[nfp] + bk);
#pragma unroll
            for (int mf = 0; mf < 4; ++mf)
#pragma unroll
                for (int nf = 0; nf < 8; ++nf)
                    mma_f16(acc[mf][nf], af[mf],
                            bf[nf >> 1][(nf & 1) * 2], bf[nf >> 1][(nf & 1) * 2 + 1]);
        }
    }

    const int g   = lane >> 2;
    const int tig = lane & 3;
    __half* hsm = reinterpret_cast<__half*>(smraw);
    if (MODE) __syncthreads();

#pragma unroll
    for (int mf = 0; mf < 4; ++mf) {
#pragma unroll
        for (int nf = 0; nf < 8; ++nf) {
#pragma unroll
            for (int h = 0; h < 2; ++h) {
                const int rl = wm + mf * 16 + g + h * 8;
                const int cl = wn + nf * 8 + 2 * tig;
                const int r = m0 + rl;
                const int c = n0 + cl;
                const size_t idx = (size_t)r * N + c;
                float v0 = acc[mf][nf][h * 2 + 0];
                float v1 = acc[mf][nf][h * 2 + 1];
                if (EPI == 1) {
                    const float2 a1 = *reinterpret_cast<const float2*>(e1 + idx);
                    const float2 a2 = *reinterpret_cast<const float2*>(e2 + idx);
                    v0 += a1.x - a2.x;
                    v1 += a1.y - a2.y;
                } else if (EPI == 2) {
                    const float2 w  = *reinterpret_cast<const float2*>(e1 + idx);
                    const float2 lr = *reinterpret_cast<const float2*>(e2 + idx);
                    const float bi  = ev0[r];
                    v0 = w.x - lr.x * (coef * (v0 + bi * ev1[c]));
                    v1 = w.y - lr.y * (coef * (v1 + bi * ev1[c + 1]));
                }
                if (MODE != 1) {
                    float o0 = v0, o1 = v1;
                    if (EPI == 2) { o0 = rnd_tf32(o0); o1 = rnd_tf32(o1); }
                    float2 out; out.x = o0; out.y = o1;
                    *reinterpret_cast<float2*>(C + idx) = out;
                }
                if (MODE) {
                    hsm[(cl + 0) * 136 + rl] = __float2half_rn(v0);
                    hsm[(cl + 1) * 136 + rl] = __float2half_rn(v1);
                }
            }
        }
    }

    if (MODE) {
        __syncthreads();
#pragma unroll
        for (int i = 0; i < 16; ++i) {
            const int chunk = tid + (i << 7);
            const int row  = chunk >> 4;          // 0..127 (col of C)
            const int c16  = (chunk & 15) << 3;   // halves
            const uint4 v = *reinterpret_cast<const uint4*>(hsm + row * 136 + c16);
            *reinterpret_cast<uint4*>(CTh + (size_t)(n0 + row) * M + m0 + c16) = v;
        }
    }
}

// ---------------------------------------------------------------------------
// fp16 symmetric Gram GEMM: Sh = A*A^T (half out), lower-triangle + mirror.
// ---------------------------------------------------------------------------
__global__ void __launch_bounds__(128, 2)
symgemmH(const __half* __restrict__ A, __half* __restrict__ Ch, int N, int K)
{
    constexpr int BK   = 64;
    constexpr int TILE = 128 * 128;
    constexpr int SS   = 2 * TILE;

    extern __shared__ __align__(128) char smraw[];
    const uint32_t sb = (uint32_t)__cvta_generic_to_shared(smraw);

    const int tid  = threadIdx.x;
    const int lane = tid & 31;
    const int wid  = tid >> 5;
    const int wm   = (wid & 1) * 64;
    const int wn   = (wid >> 1) * 64;

    const int i = blockIdx.x;
    int e = (int)((sqrtf(8.0f * (float)i + 1.0f) - 1.0f) * 0.5f);
    while ((e + 1) * (e + 2) / 2 <= i) ++e;
    while (e * (e + 1) / 2 > i) --e;
    const int by = e;
    const int bx = i - e * (e + 1) / 2;
    const int m0 = by * 128;
    const int n0 = bx * 128;

    const int lr = tid >> 3;
    const int lc = tid & 7;
    const uint32_t lOff = (uint32_t)(lr * 128 + ((lc ^ (lr & 7)) << 4));
    const __half* aG = A + (size_t)(m0 + lr) * K + lc * 8;
    const __half* bG = A + (size_t)(n0 + lr) * K + lc * 8;

    auto loadTile = [&](int t) {
        const uint32_t base = sb + (uint32_t)((t % 3) * SS);
        const __half* a = aG + (size_t)t * BK;
        const __half* b = bG + (size_t)t * BK;
#pragma unroll
        for (int ii = 0; ii < 8; ++ii)
            cp16(base + lOff + 2048u * ii, a + (size_t)(16 * ii) * K);
#pragma unroll
        for (int ii = 0; ii < 8; ++ii)
            cp16(base + TILE + lOff + 2048u * ii, b + (size_t)(16 * ii) * K);
        asm volatile("cp.async.commit_group;" ::: "memory");
    };

    const int rr  = lane & 7;
    const int loA = (lane >> 3) & 1;
    const int hiA = (lane >> 4) & 1;
    const int loB = (lane >> 4) & 1;
    const int hiB = (lane >> 3) & 1;
    const uint32_t swz = (uint32_t)rr << 4;

    uint32_t aRow[4], bRow[4];
#pragma unroll
    for (int mf = 0; mf < 4; ++mf)
        aRow[mf] = (uint32_t)((wm + mf * 16 + loA * 8 + rr) * 128);
#pragma unroll
    for (int nfp = 0; nfp < 4; ++nfp)
        bRow[nfp] = (uint32_t)((wn + nfp * 16 + loB * 8 + rr) * 128);

    float acc[4][8][4];
#pragma unroll
    for (int a = 0; a < 4; ++a)
#pragma unroll
        for (int b = 0; b < 8; ++b)
#pragma unroll
            for (int k = 0; k < 4; ++k) acc[a][b][k] = 0.0f;

    const int nt = K / BK;
    loadTile(0);
    loadTile(1);

    for (int t = 0; t < nt; ++t) {
        if (t + 1 < nt) asm volatile("cp.async.wait_group 1;" ::: "memory");
        else            asm volatile("cp.async.wait_group 0;" ::: "memory");
        __syncthreads();
        if (t + 2 < nt) loadTile(t + 2);

        const uint32_t stA = sb + (uint32_t)((t % 3) * SS);
        const uint32_t stB = stA + TILE;

#pragma unroll
        for (int kk = 0; kk < 4; ++kk) {
            const uint32_t ak = (((uint32_t)(2 * kk + hiA)) << 4) ^ swz;
            const uint32_t bk = (((uint32_t)(2 * kk + hiB)) << 4) ^ swz;
            uint32_t af[4][4];
#pragma unroll
            for (int mf = 0; mf < 4; ++mf)
                ldsm4(af[mf][0], af[mf][1], af[mf][2], af[mf][3], stA + aRow[mf] + ak);
            uint32_t bf[4][4];
#pragma unroll
            for (int nfp = 0; nfp < 4; ++nfp)
                ldsm4(bf[nfp][0], bf[nfp][1], bf[nfp][2], bf[nfp][3], stB + bRow[nfp] + bk);
#pragma unroll
            for (int mf = 0; mf < 4; ++mf)
#pragma unroll
                for (int nf = 0; nf < 8; ++nf)
                    mma_f16(acc[mf][nf], af[mf],
                            bf[nf >> 1][(nf & 1) * 2], bf[nf >> 1][(nf & 1) * 2 + 1]);
        }
    }

    const int g   = lane >> 2;
    const int tig = lane & 3;
    __half* hsm = reinterpret_cast<__half*>(smraw);
    const bool mirror = (bx != by);
    if (mirror) __syncthreads();

#pragma unroll
    for (int mf = 0; mf < 4; ++mf) {
#pragma unroll
        for (int nf = 0; nf < 8; ++nf) {
#pragma unroll
            for (int h = 0; h < 2; ++h) {
                const int rl = wm + mf * 16 + g + h * 8;
                const int cl = wn + nf * 8 + 2 * tig;
                const __half h0 = __float2half_rn(acc[mf][nf][h * 2 + 0]);
                const __half h1 = __float2half_rn(acc[mf][nf][h * 2 + 1]);
                __half2 hp; hp.x = h0; hp.y = h1;
                *reinterpret_cast<__half2*>(Ch + (size_t)(m0 + rl) * N + n0 + cl) = hp;
                if (mirror) {
                    hsm[(cl + 0) * 136 + rl] = h0;
                    hsm[(cl + 1) * 136 + rl] = h1;
                }
            }
        }
    }

    if (mirror) {
        __syncthreads();
#pragma unroll
        for (int ii = 0; ii < 16; ++ii) {
            const int chunk = tid + (ii << 7);
            const int row  = chunk >> 4;
            const int c16  = (chunk & 15) << 3;
            const uint4 v = *reinterpret_cast<const uint4*>(hsm + row * 136 + c16);
            *reinterpret_cast<uint4*>(Ch + (size_t)(n0 + row) * N + m0 + c16) = v;
        }
    }
}

// ---------------- small kernels ----------------------------------------------
__global__ void round_kernel(const float* __restrict__ in, float* __restrict__ out, int n4)
{
    int i = blockIdx.x * blockDim.x + threadIdx.x;
    if (i < n4) {
        float4 v = reinterpret_cast<const float4*>(in)[i];
        v.x = rnd_tf32(v.x); v.y = rnd_tf32(v.y);
        v.z = rnd_tf32(v.z); v.w = rnd_tf32(v.w);
        reinterpret_cast<float4*>(out)[i] = v;
    }
}

__global__ void half_kernel(const float* __restrict__ in, __half* __restrict__ out, int n)
{
    int i = blockIdx.x * blockDim.x + threadIdx.x;
    if (i < n) out[i] = __float2half_rn(in[i]);
}

// src: outR = tf32(in) fp32, outTh = half(in)^T
__global__ void prep_src(const float* __restrict__ in, float* __restrict__ outR,
                         __half* __restrict__ outTh, int R, int C)
{
    __shared__ float tile[32][33];
    const int bx = blockIdx.x * 32, by = blockIdx.y * 32;
    const int x = threadIdx.x, y = threadIdx.y;
#pragma unroll
    for (int j = 0; j < 32; j += 8) {
        const float v = in[(size_t)(by + y + j) * C + bx + x];
        tile[y + j][x] = v;
        outR[(size_t)(by + y + j) * C + bx + x] = rnd_tf32(v);
    }
    __syncthreads();
#pragma unroll
    for (int j = 0; j < 32; j += 8)
        outTh[(size_t)(bx + y + j) * R + by + x] = __float2half_rn(tile[x][y + j]);
}

// theta_k: outRh = half(in), outTh = half(in)^T
__global__ void prep_thk(const float* __restrict__ in, __half* __restrict__ outRh,
                         __half* __restrict__ outTh, int R, int C)
{
    __shared__ float tile[32][33];
    const int bx = blockIdx.x * 32, by = blockIdx.y * 32;
    const int x = threadIdx.x, y = threadIdx.y;
#pragma unroll
    for (int j = 0; j < 32; j += 8) {
        const float v = in[(size_t)(by + y + j) * C + bx + x];
        tile[y + j][x] = v;
        outRh[(size_t)(by + y + j) * C + bx + x] = __float2half_rn(v);
    }
    __syncthreads();
#pragma unroll
    for (int j = 0; j < 32; j += 8)
        outTh[(size_t)(bx + y + j) * R + by + x] = __float2half_rn(tile[x][y + j]);
}

__global__ void colsum_kernel(const float* __restrict__ in, float* __restrict__ part)
{
    int col = blockIdx.x * blockDim.x + threadIdx.x;
    int chunk = blockIdx.y;
    const float* p = in + (size_t)chunk * 128 * D_DIM + col;
    float s0 = 0.f, s1 = 0.f, s2 = 0.f, s3 = 0.f;
#pragma unroll
    for (int r = 0; r < 128; r += 4) {
        s0 += p[(size_t)(r + 0) * D_DIM];
        s1 += p[(size_t)(r + 1) * D_DIM];
        s2 += p[(size_t)(r + 2) * D_DIM];
        s3 += p[(size_t)(r + 3) * D_DIM];
    }
    part[chunk * D_DIM + col] = (s0 + s1) + (s2 + s3);
}

__global__ void creduce_kernel(const float* __restrict__ part, float* __restrict__ c)
{
    int j = blockIdx.x * blockDim.x + threadIdx.x;
    float s = 0.f;
#pragma unroll
    for (int ch = 0; ch < 32; ++ch) s += part[ch * D_DIM + j];
    c[j] = s;
}

__global__ void vecmat_kernel(const float* __restrict__ vec, const float* __restrict__ Mat,
                              float* __restrict__ outv)
{
    int j = blockIdx.x * blockDim.x + threadIdx.x;
    float s0 = 0.f, s1 = 0.f, s2 = 0.f, s3 = 0.f;
#pragma unroll 4
    for (int k = 0; k < D_DIM; k += 4) {
        s0 += vec[k + 0] * Mat[(size_t)(k + 0) * D_DIM + j];
        s1 += vec[k + 1] * Mat[(size_t)(k + 1) * D_DIM + j];
        s2 += vec[k + 2] * Mat[(size_t)(k + 2) * D_DIM + j];
        s3 += vec[k + 3] * Mat[(size_t)(k + 3) * D_DIM + j];
    }
    outv[j] = (s0 + s1) + (s2 + s3);
}

__global__ void bn_kernel(const float* __restrict__ Mm, const float* __restrict__ c,
                          const float* __restrict__ b, const float* __restrict__ lrb,
                          float* __restrict__ bn, float coef)
{
    int j = blockIdx.x * blockDim.x + threadIdx.x;
    float s0 = 0.f, s1 = 0.f, s2 = 0.f, s3 = 0.f;
#pragma unroll 4
    for (int k = 0; k < D_DIM; k += 4) {
        s0 += c[k + 0] * Mm[(size_t)(k + 0) * D_DIM + j];
        s1 += c[k + 1] * Mm[(size_t)(k + 1) * D_DIM + j];
        s2 += c[k + 2] * Mm[(size_t)(k + 2) * D_DIM + j];
        s3 += c[k + 3] * Mm[(size_t)(k + 3) * D_DIM + j];
    }
    float s = (s0 + s1) + (s2 + s3);
    bn[j] = b[j] - lrb[j] * coef * (s + (float)B_TOK * b[j]);
}

// ---------------- host --------------------------------------------------------
extern "C" void kernel_launch(void* const* d_in, const int* in_sizes, int n_in,
                              void* d_out, int out_size)
{
    const float* src  = (const float*)d_in[0];
    const float* th_k = (const float*)d_in[1];
    const float* th_q = (const float*)d_in[2];
    const float* th_v = (const float*)d_in[3];
    const float* W    = (const float*)d_in[4];
    const float* b    = (const float*)d_in[5];
    const float* lr_w = (const float*)d_in[6];
    const float* lr_b = (const float*)d_in[7];
    float* out = (float*)d_out;

    float *srcR, *thqR, *Mm, *Wn, *PT, *part, *cvec, *vvec, *bn;
    __half *srcTh, *thkRh, *thkTh, *WRh, *Sh, *MTh, *T1Th;
    cudaGetSymbolAddress((void**)&srcR,  g_srcR);
    cudaGetSymbolAddress((void**)&srcTh, g_srcTh);
    cudaGetSymbolAddress((void**)&thkRh, g_thkRh);
    cudaGetSymbolAddress((void**)&thkTh, g_thkTh);
    cudaGetSymbolAddress((void**)&WRh,   g_WRh);
    cudaGetSymbolAddress((void**)&thqR,  g_thqR);
    cudaGetSymbolAddress((void**)&Sh,    g_Sh);
    cudaGetSymbolAddress((void**)&Mm,    g_M);
    cudaGetSymbolAddress((void**)&MTh,   g_MTh);
    cudaGetSymbolAddress((void**)&T1Th,  g_T1Th);
    cudaGetSymbolAddress((void**)&Wn,    g_Wn);
    cudaGetSymbolAddress((void**)&PT,    g_PT);
    cudaGetSymbolAddress((void**)&part,  g_part);
    cudaGetSymbolAddress((void**)&cvec,  g_c);
    cudaGetSymbolAddress((void**)&vvec,  g_v);
    cudaGetSymbolAddress((void**)&bn,    g_bn);

    static cudaStream_t s2 = nullptr;
    static cudaEvent_t evFork = nullptr, evJoin = nullptr;
    if (s2 == nullptr) {
        cudaStreamCreateWithFlags(&s2, cudaStreamNonBlocking);
        cudaEventCreateWithFlags(&evFork, cudaEventDisableTiming);
        cudaEventCreateWithFlags(&evJoin, cudaEventDisableTiming);
    }

    const float coef = 2.0f / ((float)B_TOK * (float)D_DIM);
    const int SMEM = 3 * 2 * 128 * 128;   // 98304 bytes, both kernels

    cudaFuncSetAttribute(hgemm<1, 2>,          cudaFuncAttributeMaxDynamicSharedMemorySize, SMEM);
    cudaFuncSetAttribute(hgemm<0, 1>,          cudaFuncAttributeMaxDynamicSharedMemorySize, SMEM);
    cudaFuncSetAttribute(hgemm<2, 0>,          cudaFuncAttributeMaxDynamicSharedMemorySize, SMEM);
    cudaFuncSetAttribute(symgemmH,             cudaFuncAttributeMaxDynamicSharedMemorySize, SMEM);
    cudaFuncSetAttribute(ntgemm3<3, true,  2>, cudaFuncAttributeMaxDynamicSharedMemorySize, SMEM);
    cudaFuncSetAttribute(ntgemm3<4, false, 0>, cudaFuncAttributeMaxDynamicSharedMemorySize, SMEM);

    dim3 tb(32, 8);
    dim3 gridD(D_DIM / 128, D_DIM / 128);   // 256 CTAs
    dim3 gridZ(D_DIM / 128, B_TOK / 128);   // 512 CTAs
    const int nSymTiles = (D_DIM / 128) * (D_DIM / 128 + 1) / 2;   // 136

    // prep on main stream
    prep_src<<<dim3(D_DIM / 32, B_TOK / 32), tb>>>(src, srcR, srcTh, B_TOK, D_DIM);
    prep_thk<<<dim3(D_DIM / 32, D_DIM / 32), tb>>>(th_k, thkRh, thkTh, D_DIM, D_DIM);

    // fork: W half, M-GEMM (fp16), theta_q round
    cudaEventRecord(evFork, 0);
    cudaStreamWaitEvent(s2, evFork, 0);
    half_kernel<<<(D_DIM * D_DIM + 255) / 256, 256, 0, s2>>>(W, WRh, D_DIM * D_DIM);
    // M = theta_k @ W^T + theta_k - theta_v  -> Mm fp32 + MTh half
    hgemm<1, 2><<<gridD, 128, SMEM, s2>>>(thkRh, WRh, Mm, MTh, D_DIM, D_DIM, D_DIM,
                                          th_k, th_v, nullptr, nullptr, 0.f);
    round_kernel<<<(D_DIM * D_DIM / 4 + 255) / 256, 256, 0, s2>>>(th_q, thqR, D_DIM * D_DIM / 4);
    cudaEventRecord(evJoin, s2);

    // main chain
    colsum_kernel<<<dim3(D_DIM / 256, 32), 256>>>(src, part);
    symgemmH<<<nSymTiles, 128, SMEM>>>(srcTh, Sh, D_DIM, B_TOK);
    creduce_kernel<<<D_DIM / 256, 256>>>(part, cvec);
    vecmat_kernel<<<D_DIM / 128, 128>>>(cvec, th_k, vvec);

    // T1T = (S @ theta_k)^T   (fp16, half out)
    hgemm<0, 1><<<gridD, 128, SMEM>>>(Sh, thkTh, nullptr, T1Th, D_DIM, D_DIM, D_DIM,
                                      nullptr, nullptr, nullptr, nullptr, 0.f);

    cudaStreamWaitEvent(0, evJoin, 0);

    bn_kernel<<<D_DIM / 128, 128>>>(Mm, cvec, b, lr_b, bn, coef);

    // Wn = W - lr_w * coef * (M^T @ T1 + b (x) v)   (fp16 mma, fp32 epilogue)
    hgemm<2, 0><<<gridD, 128, SMEM>>>(MTh, T1Th, Wn, nullptr, D_DIM, D_DIM, D_DIM,
                                      W, lr_w, b, vvec, coef);

    // PT = (theta_q @ Wn^T + theta_q)^T   (tf32)
    ntgemm3<3, true, 2><<<gridD, 128, SMEM>>>(thqR, Wn, nullptr, PT, D_DIM, D_DIM, D_DIM,
                                              nullptr, th_q);

    // z = src @ P + bn   (tf32)
    ntgemm3<4, false, 0><<<gridZ, 128, SMEM>>>(srcR, PT, out, nullptr, B_TOK, D_DIM, D_DIM,
                                               bn, nullptr);
}

// round 12
// speedup vs baseline: 1.5486x; 1.2023x over previous
#include <cuda_runtime.h>
#include <cuda_fp16.h>
#include <cstdint>
#include <math.h>

#define D_DIM 2048
#define B_TOK 4096

// ---------------- scratch (device globals; no allocation allowed) ----------
__device__ __half g_srcRh[(size_t)B_TOK * D_DIM];  // half src (z A)
__device__ __half g_srcTh[(size_t)B_TOK * D_DIM];  // half src^T (S operand)
__device__ __half g_thkRh[(size_t)D_DIM * D_DIM];  // half theta_k (M A)
__device__ __half g_thkTh[(size_t)D_DIM * D_DIM];  // half theta_k^T (T1 B)
__device__ __half g_WRh [(size_t)D_DIM * D_DIM];   // half W (M B)
__device__ __half g_thqRh[(size_t)D_DIM * D_DIM];  // half theta_q (P A)
__device__ __half g_Sh  [(size_t)D_DIM * D_DIM];   // half S
__device__ float  g_M   [(size_t)D_DIM * D_DIM];   // fp32 M (for bn)
__device__ __half g_MTh [(size_t)D_DIM * D_DIM];   // half M^T (gW A)
__device__ __half g_T1Th[(size_t)D_DIM * D_DIM];   // half T1^T (gW B)
__device__ __half g_Wnh [(size_t)D_DIM * D_DIM];   // half Wn (P B)
__device__ __half g_PTh [(size_t)D_DIM * D_DIM];   // half P^T (z B)
__device__ float  g_part[32 * D_DIM];
__device__ float  g_c   [D_DIM];
__device__ float  g_v   [D_DIM];
__device__ float  g_bn  [D_DIM];

// ---------------- PTX helpers ----------------------------------------------
__device__ __forceinline__ void cp16(uint32_t dst, const void* src) {
    asm volatile("cp.async.cg.shared.global [%0], [%1], 16;" :: "r"(dst), "l"(src));
}

__device__ __forceinline__ void ldsm4(uint32_t& r0, uint32_t& r1, uint32_t& r2, uint32_t& r3,
                                      uint32_t addr) {
    asm volatile("ldmatrix.sync.aligned.m8n8.x4.shared.b16 {%0,%1,%2,%3}, [%4];"
                 : "=r"(r0), "=r"(r1), "=r"(r2), "=r"(r3) : "r"(addr));
}

__device__ __forceinline__ void mma_f16(float c[4], const uint32_t a[4],
                                        uint32_t b0, uint32_t b1) {
    asm volatile(
        "mma.sync.aligned.m16n8k16.row.col.f32.f16.f16.f32 "
        "{%0,%1,%2,%3}, {%4,%5,%6,%7}, {%8,%9}, {%0,%1,%2,%3};"
        : "+f"(c[0]), "+f"(c[1]), "+f"(c[2]), "+f"(c[3])
        : "r"(a[0]), "r"(a[1]), "r"(a[2]), "r"(a[3]), "r"(b0), "r"(b1));
}

// ---------------------------------------------------------------------------
// fp16 4-warp NT GEMM: C[M,N] = A[M,K]*B[N,K]^T, fp32 accumulate.
// CTA 128x128, 4 warps 64x64, BK=64 halves (128B rows), 3-stage, occ 2.
// EPI 0: v = acc
// EPI 1: v = acc + e1[idx] - e2[idx]
// EPI 2: v = e1[idx] - e2[idx]*coef*(acc + ev0[r]*ev1[c])
// EPI 3: v = acc + e1[idx]
// EPI 4: v = acc + ev0[col]
// MODE 0: fp32 C.  MODE 1: half CT only.  MODE 2: fp32 C + half CT.
// MODE 3: half Ch (non-transposed).
// ---------------------------------------------------------------------------
template <int EPI, int MODE>
__global__ void __launch_bounds__(128, 2)
hgemm(const __half* __restrict__ A, const __half* __restrict__ B,
      float* __restrict__ C, __half* __restrict__ Ch, __half* __restrict__ CTh,
      int M, int N, int K,
      const float* __restrict__ e1, const float* __restrict__ e2,
      const float* __restrict__ ev0, const float* __restrict__ ev1, float coef)
{
    constexpr int BK   = 64;             // halves
    constexpr int TILE = 128 * 128;      // bytes
    constexpr int SS   = 2 * TILE;

    extern __shared__ __align__(128) char smraw[];
    const uint32_t sb = (uint32_t)__cvta_generic_to_shared(smraw);

    const int tid  = threadIdx.x;
    const int lane = tid & 31;
    const int wid  = tid >> 5;
    const int wm   = (wid & 1) * 64;
    const int wn   = (wid >> 1) * 64;
    const int m0   = blockIdx.y * 128;
    const int n0   = blockIdx.x * 128;

    const int lr = tid >> 3;
    const int lc = tid & 7;
    const uint32_t lOff = (uint32_t)(lr * 128 + ((lc ^ (lr & 7)) << 4));
    const __half* aG = A + (size_t)(m0 + lr) * K + lc * 8;
    const __half* bG = B + (size_t)(n0 + lr) * K + lc * 8;

    auto loadTile = [&](int t) {
        const uint32_t base = sb + (uint32_t)((t % 3) * SS);
        const __half* a = aG + (size_t)t * BK;
        const __half* b = bG + (size_t)t * BK;
#pragma unroll
        for (int i = 0; i < 8; ++i)
            cp16(base + lOff + 2048u * i, a + (size_t)(16 * i) * K);
#pragma unroll
        for (int i = 0; i < 8; ++i)
            cp16(base + TILE + lOff + 2048u * i, b + (size_t)(16 * i) * K);
        asm volatile("cp.async.commit_group;" ::: "memory");
    };

    const int rr  = lane & 7;
    const int loA = (lane >> 3) & 1;
    const int hiA = (lane >> 4) & 1;
    const int loB = (lane >> 4) & 1;
    const int hiB = (lane >> 3) & 1;
    const uint32_t swz = (uint32_t)rr << 4;

    uint32_t aRow[4], bRow[4];
#pragma unroll
    for (int mf = 0; mf < 4; ++mf)
        aRow[mf] = (uint32_t)((wm + mf * 16 + loA * 8 + rr) * 128);
#pragma unroll
    for (int nfp = 0; nfp < 4; ++nfp)
        bRow[nfp] = (uint32_t)((wn + nfp * 16 + loB * 8 + rr) * 128);

    float acc[4][8][4];
#pragma unroll
    for (int i = 0; i < 4; ++i)
#pragma unroll
        for (int j = 0; j < 8; ++j)
#pragma unroll
            for (int k = 0; k < 4; ++k) acc[i][j][k] = 0.0f;

    const int nt = K / BK;
    loadTile(0);
    loadTile(1);

    for (int t = 0; t < nt; ++t) {
        if (t + 1 < nt) asm volatile("cp.async.wait_group 1;" ::: "memory");
        else            asm volatile("cp.async.wait_group 0;" ::: "memory");
        __syncthreads();
        if (t + 2 < nt) loadTile(t + 2);

        const uint32_t stA = sb + (uint32_t)((t % 3) * SS);
        const uint32_t stB = stA + TILE;

#pragma unroll
        for (int kk = 0; kk < 4; ++kk) {    // each kk = K16
            const uint32_t ak = (((uint32_t)(2 * kk + hiA)) << 4) ^ swz;
            const uint32_t bk = (((uint32_t)(2 * kk + hiB)) << 4) ^ swz;
            uint32_t af[4][4];
#pragma unroll
            for (int mf = 0; mf < 4; ++mf)
                ldsm4(af[mf][0], af[mf][1], af[mf][2], af[mf][3], stA + aRow[mf] + ak);
            uint32_t bf[4][4];
#pragma unroll
            for (int nfp = 0; nfp < 4; ++nfp)
                ldsm4(bf[nfp][0], bf[nfp][1], bf[nfp][2], bf[nfp][3], stB + bRow[nfp] + bk);
#pragma unroll
            for (int mf = 0; mf < 4; ++mf)
#pragma unroll
                for (int nf = 0; nf < 8; ++nf)
                    mma_f16(acc[mf][nf], af[mf],
                            bf[nf >> 1][(nf & 1) * 2], bf[nf >> 1][(nf & 1) * 2 + 1]);
        }
    }

    const int g   = lane >> 2;
    const int tig = lane & 3;
    __half* hsm = reinterpret_cast<__half*>(smraw);
    if (MODE == 1 || MODE == 2) __syncthreads();

#pragma unroll
    for (int mf = 0; mf < 4; ++mf) {
#pragma unroll
        for (int nf = 0; nf < 8; ++nf) {
#pragma unroll
            for (int h = 0; h < 2; ++h) {
                const int rl = wm + mf * 16 + g + h * 8;
                const int cl = wn + nf * 8 + 2 * tig;
                const int r = m0 + rl;
                const int c = n0 + cl;
                const size_t idx = (size_t)r * N + c;
                float v0 = acc[mf][nf][h * 2 + 0];
                float v1 = acc[mf][nf][h * 2 + 1];
                if (EPI == 1) {
                    const float2 a1 = *reinterpret_cast<const float2*>(e1 + idx);
                    const float2 a2 = *reinterpret_cast<const float2*>(e2 + idx);
                    v0 += a1.x - a2.x;
                    v1 += a1.y - a2.y;
                } else if (EPI == 2) {
                    const float2 w  = *reinterpret_cast<const float2*>(e1 + idx);
                    const float2 lr = *reinterpret_cast<const float2*>(e2 + idx);
                    const float bi  = ev0[r];
                    v0 = w.x - lr.x * (coef * (v0 + bi * ev1[c]));
                    v1 = w.y - lr.y * (coef * (v1 + bi * ev1[c + 1]));
                } else if (EPI == 3) {
                    const float2 a1 = *reinterpret_cast<const float2*>(e1 + idx);
                    v0 += a1.x;
                    v1 += a1.y;
                } else if (EPI == 4) {
                    v0 += ev0[c];
                    v1 += ev0[c + 1];
                }
                if (MODE == 0 || MODE == 2) {
                    float2 out; out.x = v0; out.y = v1;
                    *reinterpret_cast<float2*>(C + idx) = out;
                }
                if (MODE == 3) {
                    __half2 hp;
                    hp.x = __float2half_rn(v0);
                    hp.y = __float2half_rn(v1);
                    *reinterpret_cast<__half2*>(Ch + idx) = hp;
                }
                if (MODE == 1 || MODE == 2) {
                    hsm[(cl + 0) * 136 + rl] = __float2half_rn(v0);
                    hsm[(cl + 1) * 136 + rl] = __float2half_rn(v1);
                }
            }
        }
    }

    if (MODE == 1 || MODE == 2) {
        __syncthreads();
#pragma unroll
        for (int i = 0; i < 16; ++i) {
            const int chunk = tid + (i << 7);
            const int row  = chunk >> 4;
            const int c16  = (chunk & 15) << 3;
            const uint4 v = *reinterpret_cast<const uint4*>(hsm + row * 136 + c16);
            *reinterpret_cast<uint4*>(CTh + (size_t)(n0 + row) * M + m0 + c16) = v;
        }
    }
}

// ---------------------------------------------------------------------------
// fp16 symmetric Gram GEMM: Sh = A*A^T (half out), lower-triangle + mirror.
// ---------------------------------------------------------------------------
__global__ void __launch_bounds__(128, 2)
symgemmH(const __half* __restrict__ A, __half* __restrict__ Ch, int N, int K)
{
    constexpr int BK   = 64;
    constexpr int TILE = 128 * 128;
    constexpr int SS   = 2 * TILE;

    extern __shared__ __align__(128) char smraw[];
    const uint32_t sb = (uint32_t)__cvta_generic_to_shared(smraw);

    const int tid  = threadIdx.x;
    const int lane = tid & 31;
    const int wid  = tid >> 5;
    const int wm   = (wid & 1) * 64;
    const int wn   = (wid >> 1) * 64;

    const int i = blockIdx.x;
    int e = (int)((sqrtf(8.0f * (float)i + 1.0f) - 1.0f) * 0.5f);
    while ((e + 1) * (e + 2) / 2 <= i) ++e;
    while (e * (e + 1) / 2 > i) --e;
    const int by = e;
    const int bx = i - e * (e + 1) / 2;
    const int m0 = by * 128;
    const int n0 = bx * 128;

    const int lr = tid >> 3;
    const int lc = tid & 7;
    const uint32_t lOff = (uint32_t)(lr * 128 + ((lc ^ (lr & 7)) << 4));
    const __half* aG = A + (size_t)(m0 + lr) * K + lc * 8;
    const __half* bG = A + (size_t)(n0 + lr) * K + lc * 8;

    auto loadTile = [&](int t) {
        const uint32_t base = sb + (uint32_t)((t % 3) * SS);
        const __half* a = aG + (size_t)t * BK;
        const __half* b = bG + (size_t)t * BK;
#pragma unroll
        for (int ii = 0; ii < 8; ++ii)
            cp16(base + lOff + 2048u * ii, a + (size_t)(16 * ii) * K);
#pragma unroll
        for (int ii = 0; ii < 8; ++ii)
            cp16(base + TILE + lOff + 2048u * ii, b + (size_t)(16 * ii) * K);
        asm volatile("cp.async.commit_group;" ::: "memory");
    };

    const int rr  = lane & 7;
    const int loA = (lane >> 3) & 1;
    const int hiA = (lane >> 4) & 1;
    const int loB = (lane >> 4) & 1;
    const int hiB = (lane >> 3) & 1;
    const uint32_t swz = (uint32_t)rr << 4;

    uint32_t aRow[4], bRow[4];
#pragma unroll
    for (int mf = 0; mf < 4; ++mf)
        aRow[mf] = (uint32_t)((wm + mf * 16 + loA * 8 + rr) * 128);
#pragma unroll
    for (int nfp = 0; nfp < 4; ++nfp)
        bRow[nfp] = (uint32_t)((wn + nfp * 16 + loB * 8 + rr) * 128);

    float acc[4][8][4];
#pragma unroll
    for (int a = 0; a < 4; ++a)
#pragma unroll
        for (int b = 0; b < 8; ++b)
#pragma unroll
            for (int k = 0; k < 4; ++k) acc[a][b][k] = 0.0f;

    const int nt = K / BK;
    loadTile(0);
    loadTile(1);

    for (int t = 0; t < nt; ++t) {
        if (t + 1 < nt) asm volatile("cp.async.wait_group 1;" ::: "memory");
        else            asm volatile("cp.async.wait_group 0;" ::: "memory");
        __syncthreads();
        if (t + 2 < nt) loadTile(t + 2);

        const uint32_t stA = sb + (uint32_t)((t % 3) * SS);
        const uint32_t stB = stA + TILE;

#pragma unroll
        for (int kk = 0; kk < 4; ++kk) {
            const uint32_t ak = (((uint32_t)(2 * kk + hiA)) << 4) ^ swz;
            const uint32_t bk = (((uint32_t)(2 * kk + hiB)) << 4) ^ swz;
            uint32_t af[4][4];
#pragma unroll
            for (int mf = 0; mf < 4; ++mf)
                ldsm4(af[mf][0], af[mf][1], af[mf][2], af[mf][3], stA + aRow[mf] + ak);
            uint32_t bf[4][4];
#pragma unroll
            for (int nfp = 0; nfp < 4; ++nfp)
                ldsm4(bf[nfp][0], bf[nfp][1], bf[nfp][2], bf[nfp][3], stB + bRow[nfp] + bk);
#pragma unroll
            for (int mf = 0; mf < 4; ++mf)
#pragma unroll
                for (int nf = 0; nf < 8; ++nf)
                    mma_f16(acc[mf][nf], af[mf],
                            bf[nf >> 1][(nf & 1) * 2], bf[nf >> 1][(nf & 1) * 2 + 1]);
        }
    }

    const int g   = lane >> 2;
    const int tig = lane & 3;
    __half* hsm = reinterpret_cast<__half*>(smraw);
    const bool mirror = (bx != by);
    if (mirror) __syncthreads();

#pragma unroll
    for (int mf = 0; mf < 4; ++mf) {
#pragma unroll
        for (int nf = 0; nf < 8; ++nf) {
#pragma unroll
            for (int h = 0; h < 2; ++h) {
                const int rl = wm + mf * 16 + g + h * 8;
                const int cl = wn + nf * 8 + 2 * tig;
                const __half h0 = __float2half_rn(acc[mf][nf][h * 2 + 0]);
                const __half h1 = __float2half_rn(acc[mf][nf][h * 2 + 1]);
                __half2 hp; hp.x = h0; hp.y = h1;
                *reinterpret_cast<__half2*>(Ch + (size_t)(m0 + rl) * N + n0 + cl) = hp;
                if (mirror) {
                    hsm[(cl + 0) * 136 + rl] = h0;
                    hsm[(cl + 1) * 136 + rl] = h1;
                }
            }
        }
    }

    if (mirror) {
        __syncthreads();
#pragma unroll
        for (int ii = 0; ii < 16; ++ii) {
            const int chunk = tid + (ii << 7);
            const int row  = chunk >> 4;
            const int c16  = (chunk & 15) << 3;
            const uint4 v = *reinterpret_cast<const uint4*>(hsm + row * 136 + c16);
            *reinterpret_cast<uint4*>(Ch + (size_t)(n0 + row) * N + m0 + c16) = v;
        }
    }
}

// ---------------- small kernels ----------------------------------------------
__global__ void half_kernel(const float* __restrict__ in, __half* __restrict__ out, int n)
{
    int i = blockIdx.x * blockDim.x + threadIdx.x;
    if (i < n) out[i] = __float2half_rn(in[i]);
}

// outRh = half(in), outTh = half(in)^T
__global__ void prep_dual(const float* __restrict__ in, __half* __restrict__ outRh,
                          __half* __restrict__ outTh, int R, int C)
{
    __shared__ float tile[32][33];
    const int bx = blockIdx.x * 32, by = blockIdx.y * 32;
    const int x = threadIdx.x, y = threadIdx.y;
#pragma unroll
    for (int j = 0; j < 32; j += 8) {
        const float v = in[(size_t)(by + y + j) * C + bx + x];
        tile[y + j][x] = v;
        outRh[(size_t)(by + y + j) * C + bx + x] = __float2half_rn(v);
    }
    __syncthreads();
#pragma unroll
    for (int j = 0; j < 32; j += 8)
        outTh[(size_t)(bx + y + j) * R + by + x] = __float2half_rn(tile[x][y + j]);
}

__global__ void colsum_kernel(const float* __restrict__ in, float* __restrict__ part)
{
    int col = blockIdx.x * blockDim.x + threadIdx.x;
    int chunk = blockIdx.y;
    const float* p = in + (size_t)chunk * 128 * D_DIM + col;
    float s0 = 0.f, s1 = 0.f, s2 = 0.f, s3 = 0.f;
#pragma unroll
    for (int r = 0; r < 128; r += 4) {
        s0 += p[(size_t)(r + 0) * D_DIM];
        s1 += p[(size_t)(r + 1) * D_DIM];
        s2 += p[(size_t)(r + 2) * D_DIM];
        s3 += p[(size_t)(r + 3) * D_DIM];
    }
    part[chunk * D_DIM + col] = (s0 + s1) + (s2 + s3);
}

__global__ void creduce_kernel(const float* __restrict__ part, float* __restrict__ c)
{
    int j = blockIdx.x * blockDim.x + threadIdx.x;
    float s = 0.f;
#pragma unroll
    for (int ch = 0; ch < 32; ++ch) s += part[ch * D_DIM + j];
    c[j] = s;
}

__global__ void vecmat_kernel(const float* __restrict__ vec, const float* __restrict__ Mat,
                              float* __restrict__ outv)
{
    int j = blockIdx.x * blockDim.x + threadIdx.x;
    float s0 = 0.f, s1 = 0.f, s2 = 0.f, s3 = 0.f;
#pragma unroll 4
    for (int k = 0; k < D_DIM; k += 4) {
        s0 += vec[k + 0] * Mat[(size_t)(k + 0) * D_DIM + j];
        s1 += vec[k + 1] * Mat[(size_t)(k + 1) * D_DIM + j];
        s2 += vec[k + 2] * Mat[(size_t)(k + 2) * D_DIM + j];
        s3 += vec[k + 3] * Mat[(size_t)(k + 3) * D_DIM + j];
    }
    outv[j] = (s0 + s1) + (s2 + s3);
}

__global__ void bn_kernel(const float* __restrict__ Mm, const float* __restrict__ c,
                          const float* __restrict__ b, const float* __restrict__ lrb,
                          float* __restrict__ bn, float coef)
{
    int j = blockIdx.x * blockDim.x + threadIdx.x;
    float s0 = 0.f, s1 = 0.f, s2 = 0.f, s3 = 0.f;
#pragma unroll 4
    for (int k = 0; k < D_DIM; k += 4) {
        s0 += c[k + 0] * Mm[(size_t)(k + 0) * D_DIM + j];
        s1 += c[k + 1] * Mm[(size_t)(k + 1) * D_DIM + j];
        s2 += c[k + 2] * Mm[(size_t)(k + 2) * D_DIM + j];
        s3 += c[k + 3] * Mm[(size_t)(k + 3) * D_DIM + j];
    }
    float s = (s0 + s1) + (s2 + s3);
    bn[j] = b[j] - lrb[j] * coef * (s + (float)B_TOK * b[j]);
}

// ---------------- host --------------------------------------------------------
extern "C" void kernel_launch(void* const* d_in, const int* in_sizes, int n_in,
                              void* d_out, int out_size)
{
    const float* src  = (const float*)d_in[0];
    const float* th_k = (const float*)d_in[1];
    const float* th_q = (const float*)d_in[2];
    const float* th_v = (const float*)d_in[3];
    const float* W    = (const float*)d_in[4];
    const float* b    = (const float*)d_in[5];
    const float* lr_w = (const float*)d_in[6];
    const float* lr_b = (const float*)d_in[7];
    float* out = (float*)d_out;

    float *Mm, *part, *cvec, *vvec, *bn;
    __half *srcRh, *srcTh, *thkRh, *thkTh, *WRh, *thqRh, *Sh, *MTh, *T1Th, *Wnh, *PTh;
    cudaGetSymbolAddress((void**)&srcRh, g_srcRh);
    cudaGetSymbolAddress((void**)&srcTh, g_srcTh);
    cudaGetSymbolAddress((void**)&thkRh, g_thkRh);
    cudaGetSymbolAddress((void**)&thkTh, g_thkTh);
    cudaGetSymbolAddress((void**)&WRh,   g_WRh);
    cudaGetSymbolAddress((void**)&thqRh, g_thqRh);
    cudaGetSymbolAddress((void**)&Sh,    g_Sh);
    cudaGetSymbolAddress((void**)&Mm,    g_M);
    cudaGetSymbolAddress((void**)&MTh,   g_MTh);
    cudaGetSymbolAddress((void**)&T1Th,  g_T1Th);
    cudaGetSymbolAddress((void**)&Wnh,   g_Wnh);
    cudaGetSymbolAddress((void**)&PTh,   g_PTh);
    cudaGetSymbolAddress((void**)&part,  g_part);
    cudaGetSymbolAddress((void**)&cvec,  g_c);
    cudaGetSymbolAddress((void**)&vvec,  g_v);
    cudaGetSymbolAddress((void**)&bn,    g_bn);

    static cudaStream_t s2 = nullptr;
    static cudaEvent_t evFork = nullptr, evJoin = nullptr;
    if (s2 == nullptr) {
        cudaStreamCreateWithFlags(&s2, cudaStreamNonBlocking);
        cudaEventCreateWithFlags(&evFork, cudaEventDisableTiming);
        cudaEventCreateWithFlags(&evJoin, cudaEventDisableTiming);
    }

    const float coef = 2.0f / ((float)B_TOK * (float)D_DIM);
    const int SMEM = 3 * 2 * 128 * 128;   // 98304

    cudaFuncSetAttribute(hgemm<1, 2>, cudaFuncAttributeMaxDynamicSharedMemorySize, SMEM);
    cudaFuncSetAttribute(hgemm<0, 1>, cudaFuncAttributeMaxDynamicSharedMemorySize, SMEM);
    cudaFuncSetAttribute(hgemm<2, 3>, cudaFuncAttributeMaxDynamicSharedMemorySize, SMEM);
    cudaFuncSetAttribute(hgemm<3, 1>, cudaFuncAttributeMaxDynamicSharedMemorySize, SMEM);
    cudaFuncSetAttribute(hgemm<4, 0>, cudaFuncAttributeMaxDynamicSharedMemorySize, SMEM);
    cudaFuncSetAttribute(symgemmH,    cudaFuncAttributeMaxDynamicSharedMemorySize, SMEM);

    dim3 tb(32, 8);
    dim3 gridD(D_DIM / 128, D_DIM / 128);   // 256 CTAs
    dim3 gridZ(D_DIM / 128, B_TOK / 128);   // 512 CTAs
    const int nSymTiles = (D_DIM / 128) * (D_DIM / 128 + 1) / 2;   // 136

    // prep on main stream
    prep_dual<<<dim3(D_DIM / 32, B_TOK / 32), tb>>>(src, srcRh, srcTh, B_TOK, D_DIM);
    prep_dual<<<dim3(D_DIM / 32, D_DIM / 32), tb>>>(th_k, thkRh, thkTh, D_DIM, D_DIM);

    // fork: W half, M-GEMM, theta_q half
    cudaEventRecord(evFork, 0);
    cudaStreamWaitEvent(s2, evFork, 0);
    half_kernel<<<(D_DIM * D_DIM + 255) / 256, 256, 0, s2>>>(W, WRh, D_DIM * D_DIM);
    // M = theta_k @ W^T + theta_k - theta_v  -> Mm fp32 + MTh half
    hgemm<1, 2><<<gridD, 128, SMEM, s2>>>(thkRh, WRh, Mm, nullptr, MTh, D_DIM, D_DIM, D_DIM,
                                          th_k, th_v, nullptr, nullptr, 0.f);
    half_kernel<<<(D_DIM * D_DIM + 255) / 256, 256, 0, s2>>>(th_q, thqRh, D_DIM * D_DIM);
    cudaEventRecord(evJoin, s2);

    // main chain
    colsum_kernel<<<dim3(D_DIM / 256, 32), 256>>>(src, part);
    symgemmH<<<nSymTiles, 128, SMEM>>>(srcTh, Sh, D_DIM, B_TOK);
    creduce_kernel<<<D_DIM / 256, 256>>>(part, cvec);
    vecmat_kernel<<<D_DIM / 128, 128>>>(cvec, th_k, vvec);

    // T1T = (S @ theta_k)^T   (half out, transposed)
    hgemm<0, 1><<<gridD, 128, SMEM>>>(Sh, thkTh, nullptr, nullptr, T1Th, D_DIM, D_DIM, D_DIM,
                                      nullptr, nullptr, nullptr, nullptr, 0.f);

    cudaStreamWaitEvent(0, evJoin, 0);

    bn_kernel<<<D_DIM / 128, 128>>>(Mm, cvec, b, lr_b, bn, coef);

    // Wnh = half( W - lr_w * coef * (M^T @ T1 + b (x) v) )
    hgemm<2, 3><<<gridD, 128, SMEM>>>(MTh, T1Th, nullptr, Wnh, nullptr, D_DIM, D_DIM, D_DIM,
                                      W, lr_w, b, vvec, coef);

    // PTh = half( (theta_q @ Wn^T + theta_q)^T )
    hgemm<3, 1><<<gridD, 128, SMEM>>>(thqRh, Wnh, nullptr, nullptr, PTh, D_DIM, D_DIM, D_DIM,
                                      th_q, nullptr, nullptr, nullptr, 0.f);

    // z = src @ P + bn   (fp32 out)
    hgemm<4, 0><<<gridZ, 128, SMEM>>>(srcRh, PTh, out, nullptr, nullptr, B_TOK, D_DIM, D_DIM,
                                      nullptr, nullptr, bn, nullptr, 0.f);
}